// round 3
// baseline (speedup 1.0000x reference)
#include <cuda_runtime.h>
#include <cstdint>

// ---------------------------------------------------------------------------
// Problem constants
// ---------------------------------------------------------------------------
#define B_   2
#define N_   65536
#define M_   16384
#define C1_  128
#define C2_  256
#define H1_  256
#define H2_  128
#define NT_  512        // grid.x of the stats GEMMs (65536/128)
#define EPS_ 1e-5f

// ---------------------------------------------------------------------------
// Scratch (device globals -- no allocation allowed)
// ---------------------------------------------------------------------------
__device__ __align__(16) float4 g_kpack[B_ * M_];
__device__ int    g_idx[B_ * N_];
__device__ float  g_P[(size_t)B_ * H1_ * M_];
__device__ float  g_h[(size_t)B_ * H1_ * N_];
__device__ float  g_part1[(size_t)B_ * H1_ * NT_ * 2];
__device__ float  g_part2[(size_t)B_ * H2_ * NT_ * 2];
__device__ float  g_scale1[H1_], g_bias1[H1_];
__device__ float  g_scale2[H2_], g_bias2[H2_];

// ---------------------------------------------------------------------------
// cp.async helpers
// ---------------------------------------------------------------------------
__device__ __forceinline__ uint32_t smem_u32(const void* p) {
    return (uint32_t)__cvta_generic_to_shared(p);
}
__device__ __forceinline__ void cpa16(uint32_t s, const void* g) {
    asm volatile("cp.async.cg.shared.global [%0], [%1], 16;\n" :: "r"(s), "l"(g));
}
__device__ __forceinline__ void cpa4(uint32_t s, const void* g) {
    asm volatile("cp.async.ca.shared.global [%0], [%1], 4;\n" :: "r"(s), "l"(g));
}
__device__ __forceinline__ void cpa_commit() {
    asm volatile("cp.async.commit_group;\n" ::: "memory");
}

// ---------------------------------------------------------------------------
// K0: pack known points (x, y, z, k2), k2 = (x*x + y*y) + z*z, per-op fp32
// ---------------------------------------------------------------------------
__global__ void prep_kernel(const float* __restrict__ known) {
    int j = blockIdx.x * 256 + threadIdx.x;
    if (j < B_ * M_) {
        float kx = known[3 * j + 0];
        float ky = known[3 * j + 1];
        float kz = known[3 * j + 2];
        float k2 = __fadd_rn(__fadd_rn(__fmul_rn(kx, kx), __fmul_rn(ky, ky)),
                             __fmul_rn(kz, kz));
        g_kpack[j] = make_float4(kx, ky, kz, k2);
    }
}

// ---------------------------------------------------------------------------
// K1: brute-force 1-NN, bitwise-matching reference arithmetic.
//   dot = fmaf(uz,kz, fmaf(uy,ky, ux*kx))
//   d   = (u2 - 2*dot) + k2
// fmaf(-2,dot,u2) == fsub(u2, fmul(2,dot)) bitwise (2*dot exact, one rounding).
// 256 threads, 4 unknowns/thread, grid (64, B): one full wave of 128 CTAs.
// ---------------------------------------------------------------------------
#define NN_CHUNK 2048
__global__ void __launch_bounds__(256) nn_kernel(const float* __restrict__ unknown) {
    __shared__ __align__(16) float4 sk[NN_CHUNK];
    const int b  = blockIdx.y;
    const int i0 = blockIdx.x * 1024;
    const int t  = threadIdx.x;

    float ux[4], uy[4], uz[4], u2[4], bd[4];
    int   bi[4];
#pragma unroll
    for (int u = 0; u < 4; u++) {
        int i = i0 + t + u * 256;
        const float* up = unknown + ((size_t)b * N_ + i) * 3;
        ux[u] = up[0]; uy[u] = up[1]; uz[u] = up[2];
        u2[u] = __fadd_rn(__fadd_rn(__fmul_rn(ux[u], ux[u]), __fmul_rn(uy[u], uy[u])),
                          __fmul_rn(uz[u], uz[u]));
        bd[u] = 3.4e38f; bi[u] = 0;
    }

    const float4* gk = g_kpack + (size_t)b * M_;
    for (int c0 = 0; c0 < M_; c0 += NN_CHUNK) {
        __syncthreads();
#pragma unroll
        for (int j = 0; j < NN_CHUNK / 256; j++)
            sk[t + j * 256] = gk[c0 + t + j * 256];
        __syncthreads();

#pragma unroll 4
        for (int k = 0; k < NN_CHUNK; k++) {
            float4 kp = sk[k];
#pragma unroll
            for (int u = 0; u < 4; u++) {
                float dot = __fmul_rn(ux[u], kp.x);
                dot = fmaf(uy[u], kp.y, dot);
                dot = fmaf(uz[u], kp.z, dot);
                float d = __fadd_rn(fmaf(-2.0f, dot, u2[u]), kp.w);
                if (d < bd[u]) { bd[u] = d; bi[u] = c0 + k; }
            }
        }
    }
#pragma unroll
    for (int u = 0; u < 4; u++)
        g_idx[(size_t)b * N_ + i0 + t + u * 256] = bi[u];
}

// ---------------------------------------------------------------------------
// Fused SIMT GEMM, cp.async double-buffered:
//   Y[b,o,i] = sum_c W[o, woff+c] * X[b,c,i]  (+ P[b,o,idx[b,i]] if GATHER)
//   STATS: per-CTA deterministic (sum, sumsq) partials per output channel.
// Tile 128x128, BK=16, 256 threads, 8x8 microtile.
// ---------------------------------------------------------------------------
template <int KDIM, bool GATHER, bool STATS, int MTOT>
__global__ void __launch_bounds__(256, 2) gemm_kernel(
    const float* __restrict__ W, int ldw, int woff,
    const float* __restrict__ X, int N,
    const float* __restrict__ P,
    const int*   __restrict__ idx,
    float* __restrict__ Y,
    float* __restrict__ part)
{
    __shared__ __align__(16) float Ws[2][16][132];
    __shared__ __align__(16) float Xs[2][16][132];

    const int b   = blockIdx.z;
    const int ob0 = blockIdx.y * 128;
    const int ib0 = blockIdx.x * 128;
    const int t   = threadIdx.x;
    const int tr  = t & 15;
    const int tc  = t >> 4;

    const float* Wp = W + woff;
    const float* Xb = X + (size_t)b * KDIM * N;

    const int wc  = t & 15, wr0 = t >> 4;     // W load mapping
    const int xc  = (t & 31) * 4, xr0 = t >> 5; // X load mapping

    auto issue = [&](int kt, int buf) {
        int k0 = kt * 16;
#pragma unroll
        for (int j = 0; j < 8; j++) {
            int r = wr0 + j * 16;
            cpa4(smem_u32(&Ws[buf][wc][r]), Wp + (size_t)(ob0 + r) * ldw + k0 + wc);
        }
#pragma unroll
        for (int j = 0; j < 2; j++) {
            int kr = xr0 + j * 8;
            cpa16(smem_u32(&Xs[buf][kr][xc]), Xb + (size_t)(k0 + kr) * N + ib0 + xc);
        }
        cpa_commit();
    };

    float acc[8][8];
#pragma unroll
    for (int j = 0; j < 8; j++)
#pragma unroll
        for (int i = 0; i < 8; i++) acc[j][i] = 0.f;

    constexpr int NKT = KDIM / 16;
    issue(0, 0);
    int buf = 0;
    for (int kt = 0; kt < NKT; ++kt) {
        if (kt + 1 < NKT) {
            issue(kt + 1, buf ^ 1);
            asm volatile("cp.async.wait_group 1;\n" ::: "memory");
        } else {
            asm volatile("cp.async.wait_group 0;\n" ::: "memory");
        }
        __syncthreads();
#pragma unroll
        for (int kk = 0; kk < 16; kk++) {
            float a[8], x[8];
            *(float4*)(a)     = *(const float4*)(&Ws[buf][kk][tc * 8]);
            *(float4*)(a + 4) = *(const float4*)(&Ws[buf][kk][tc * 8 + 4]);
            *(float4*)(x)     = *(const float4*)(&Xs[buf][kk][tr * 8]);
            *(float4*)(x + 4) = *(const float4*)(&Xs[buf][kk][tr * 8 + 4]);
#pragma unroll
            for (int j = 0; j < 8; j++)
#pragma unroll
                for (int i = 0; i < 8; i++)
                    acc[j][i] = fmaf(a[j], x[i], acc[j][i]);
        }
        __syncthreads();
        buf ^= 1;
    }

    if (GATHER) {
        int id[8];
#pragma unroll
        for (int i = 0; i < 8; i++)
            id[i] = idx[(size_t)b * N + ib0 + tr * 8 + i];
#pragma unroll
        for (int j = 0; j < 8; j++) {
            const float* Pr = P + ((size_t)b * MTOT + ob0 + tc * 8 + j) * M_;
#pragma unroll
            for (int i = 0; i < 8; i++)
                acc[j][i] += __ldg(&Pr[id[i]]);
        }
    }

#pragma unroll
    for (int j = 0; j < 8; j++) {
        float* Yr = Y + ((size_t)b * MTOT + ob0 + tc * 8 + j) * N + ib0 + tr * 8;
        *(float4*)(Yr)     = *(float4*)(&acc[j][0]);
        *(float4*)(Yr + 4) = *(float4*)(&acc[j][4]);
    }

    if (STATS) {
        // s1 into sA, s2 into sB; one barrier; halves of the block reduce each.
        float* sA = &Ws[0][0][0];        // 2048 floats
        float* sB = sA + 2048;           // 2048 floats (Ws has 4224 total)
#pragma unroll
        for (int j = 0; j < 8; j++) {
            float a = 0.f, q = 0.f;
#pragma unroll
            for (int i = 0; i < 8; i++) {
                a += acc[j][i];
                q = fmaf(acc[j][i], acc[j][i], q);
            }
            sA[(tc * 8 + j) * 16 + tr] = a;
            sB[(tc * 8 + j) * 16 + tr] = q;
        }
        __syncthreads();
        if (t < 128) {
            float tot = 0.f;
#pragma unroll
            for (int r = 0; r < 16; r++) tot += sA[t * 16 + r];
            part[(((size_t)b * MTOT + ob0 + t) * gridDim.x + blockIdx.x) * 2 + 0] = tot;
        } else {
            int o = t - 128;
            float tot = 0.f;
#pragma unroll
            for (int r = 0; r < 16; r++) tot += sB[o * 16 + r];
            part[(((size_t)b * MTOT + ob0 + o) * gridDim.x + blockIdx.x) * 2 + 1] = tot;
        }
    }
}

// ---------------------------------------------------------------------------
// Finalize BN stats: one block per channel
// ---------------------------------------------------------------------------
template <int MTOT>
__global__ void __launch_bounds__(128) fin_kernel(
    const float* __restrict__ part,
    const float* __restrict__ gamma, const float* __restrict__ beta,
    float* __restrict__ sc, float* __restrict__ bi, float invN)
{
    const int o = blockIdx.x;
    const int t = threadIdx.x;
    float s1 = 0.f, s2 = 0.f;
    for (int b = 0; b < B_; b++) {
        const float* p = part + ((size_t)b * MTOT + o) * NT_ * 2;
        for (int q = t; q < NT_; q += 128) {
            s1 += p[q * 2 + 0];
            s2 += p[q * 2 + 1];
        }
    }
#pragma unroll
    for (int off = 16; off; off >>= 1) {
        s1 += __shfl_down_sync(0xffffffffu, s1, off);
        s2 += __shfl_down_sync(0xffffffffu, s2, off);
    }
    __shared__ float r1[4], r2[4];
    if ((t & 31) == 0) { r1[t >> 5] = s1; r2[t >> 5] = s2; }
    __syncthreads();
    if (t == 0) {
        s1 = r1[0] + r1[1] + r1[2] + r1[3];
        s2 = r2[0] + r2[1] + r2[2] + r2[3];
        float mean = s1 * invN;
        float var  = s2 * invN - mean * mean;
        float rstd = rsqrtf(var + EPS_);
        float s    = gamma[o] * rstd;
        sc[o] = s;
        bi[o] = beta[o] - mean * s;
    }
}

// ---------------------------------------------------------------------------
// Elementwise y = relu(y*sc[ch] + bi[ch]) in place; rows of length N_
// ---------------------------------------------------------------------------
template <int CH>
__global__ void __launch_bounds__(256) bnapply_kernel(
    float* __restrict__ Y, const float* __restrict__ sc, const float* __restrict__ bi)
{
    int row = blockIdx.y;
    int ch  = row & (CH - 1);
    size_t base = (size_t)row * N_;
    int i = (blockIdx.x * 256 + threadIdx.x) * 4;
    float4 v = *(float4*)(Y + base + i);
    float s = sc[ch], b = bi[ch];
    v.x = fmaxf(fmaf(v.x, s, b), 0.f);
    v.y = fmaxf(fmaf(v.y, s, b), 0.f);
    v.z = fmaxf(fmaf(v.z, s, b), 0.f);
    v.w = fmaxf(fmaf(v.w, s, b), 0.f);
    *(float4*)(Y + base + i) = v;
}

// ---------------------------------------------------------------------------
// Launch
// ---------------------------------------------------------------------------
extern "C" void kernel_launch(void* const* d_in, const int* in_sizes, int n_in,
                              void* d_out, int out_size)
{
    const float* unknown = (const float*)d_in[0];
    const float* known   = (const float*)d_in[1];
    const float* uf      = (const float*)d_in[2];
    const float* kf      = (const float*)d_in[3];
    const float* w1      = (const float*)d_in[4];
    const float* gamma1  = (const float*)d_in[5];
    const float* beta1   = (const float*)d_in[6];
    const float* w2      = (const float*)d_in[7];
    const float* gamma2  = (const float*)d_in[8];
    const float* beta2   = (const float*)d_in[9];
    float* out = (float*)d_out;

    float *pP, *ph, *pp1, *pp2, *ps1, *pb1, *ps2, *pb2;
    int* pidx;
    cudaGetSymbolAddress((void**)&pP,   g_P);
    cudaGetSymbolAddress((void**)&ph,   g_h);
    cudaGetSymbolAddress((void**)&pp1,  g_part1);
    cudaGetSymbolAddress((void**)&pp2,  g_part2);
    cudaGetSymbolAddress((void**)&ps1,  g_scale1);
    cudaGetSymbolAddress((void**)&pb1,  g_bias1);
    cudaGetSymbolAddress((void**)&ps2,  g_scale2);
    cudaGetSymbolAddress((void**)&pb2,  g_bias2);
    cudaGetSymbolAddress((void**)&pidx, g_idx);

    const float invN = 1.0f / (float)(B_ * N_);

    prep_kernel<<<(B_ * M_ + 255) / 256, 256>>>(known);

    nn_kernel<<<dim3(N_ / 1024, B_), 256>>>(unknown);

    // P = w1[:, :256] @ known_feats
    gemm_kernel<C2_, false, false, H1_>
        <<<dim3(M_ / 128, H1_ / 128, B_), 256>>>(
            w1, 384, 0, kf, M_, nullptr, nullptr, pP, nullptr);

    // h = w1[:, 256:] @ unknow_feats + gather(P, idx); stats1
    gemm_kernel<C1_, true, true, H1_>
        <<<dim3(N_ / 128, H1_ / 128, B_), 256>>>(
            w1, 384, C2_, uf, N_, pP, pidx, ph, pp1);

    fin_kernel<H1_><<<H1_, 128>>>(pp1, gamma1, beta1, ps1, pb1, invN);

    // h = relu(bn1(h)) in place
    bnapply_kernel<H1_><<<dim3(N_ / 1024, B_ * H1_), 256>>>(ph, ps1, pb1);

    // out_pre = w2 @ h; stats2
    gemm_kernel<H1_, false, true, H2_>
        <<<dim3(N_ / 128, H2_ / 128, B_), 256>>>(
            w2, 256, 0, ph, N_, nullptr, nullptr, out, pp2);

    fin_kernel<H2_><<<H2_, 128>>>(pp2, gamma2, beta2, ps2, pb2, invN);

    // out = relu(bn2(out)) in place
    bnapply_kernel<H2_><<<dim3(N_ / 1024, B_ * H2_), 256>>>(out, ps2, pb2);
}

// round 4
// speedup vs baseline: 1.5001x; 1.5001x over previous
#include <cuda_runtime.h>
#include <cstdint>

// ---------------------------------------------------------------------------
// Problem constants
// ---------------------------------------------------------------------------
#define B_   2
#define N_   65536
#define M_   16384
#define C1_  128
#define C2_  256
#define H1_  256
#define H2_  128
#define NT_  512        // grid.x of the stats GEMMs (65536/128)
#define EPS_ 1e-5f

// ---------------------------------------------------------------------------
// Scratch (device globals -- no allocation allowed)
// ---------------------------------------------------------------------------
__device__ __align__(16) float4 g_kpack[B_ * M_];
__device__ int    g_idx[B_ * N_];
__device__ float  g_P[(size_t)B_ * H1_ * M_];
__device__ float  g_h[(size_t)B_ * H1_ * N_];
__device__ float  g_part1[(size_t)B_ * H1_ * NT_ * 2];
__device__ float  g_part2[(size_t)B_ * H2_ * NT_ * 2];
__device__ float  g_scale1[H1_], g_bias1[H1_];
__device__ float  g_scale2[H2_], g_bias2[H2_];

// ---------------------------------------------------------------------------
// K0: pack known points (x, y, z, k2), k2 = (x*x + y*y) + z*z, per-op fp32
// ---------------------------------------------------------------------------
__global__ void prep_kernel(const float* __restrict__ known) {
    int j = blockIdx.x * 256 + threadIdx.x;
    if (j < B_ * M_) {
        float kx = known[3 * j + 0];
        float ky = known[3 * j + 1];
        float kz = known[3 * j + 2];
        float k2 = __fadd_rn(__fadd_rn(__fmul_rn(kx, kx), __fmul_rn(ky, ky)),
                             __fmul_rn(kz, kz));
        g_kpack[j] = make_float4(kx, ky, kz, k2);
    }
}

// ---------------------------------------------------------------------------
// K1: brute-force 1-NN, bitwise-matching reference arithmetic:
//   dot = fmaf(uz,kz, fmaf(uy,ky, ux*kx))
//   d   = (u2 - 2*dot) + k2   [fmaf(-2,dot,u2) == fsub(u2,fmul(2,dot)) bitwise]
//   first-min under strict <, ascending k.
// 256 threads, 4 unknowns/thread, grid (64, B): one wave of 128 CTAs.
// ---------------------------------------------------------------------------
#define NN_CHUNK 2048
__global__ void __launch_bounds__(256) nn_kernel(const float* __restrict__ unknown) {
    __shared__ __align__(16) float4 sk[NN_CHUNK];
    const int b  = blockIdx.y;
    const int i0 = blockIdx.x * 1024;
    const int t  = threadIdx.x;

    float ux[4], uy[4], uz[4], u2[4], bd[4];
    int   bi[4];
#pragma unroll
    for (int u = 0; u < 4; u++) {
        int i = i0 + t + u * 256;
        const float* up = unknown + ((size_t)b * N_ + i) * 3;
        ux[u] = up[0]; uy[u] = up[1]; uz[u] = up[2];
        u2[u] = __fadd_rn(__fadd_rn(__fmul_rn(ux[u], ux[u]), __fmul_rn(uy[u], uy[u])),
                          __fmul_rn(uz[u], uz[u]));
        bd[u] = 3.4e38f; bi[u] = 0;
    }

    const float4* gk = g_kpack + (size_t)b * M_;
    for (int c0 = 0; c0 < M_; c0 += NN_CHUNK) {
        __syncthreads();
#pragma unroll
        for (int j = 0; j < NN_CHUNK / 256; j++)
            sk[t + j * 256] = gk[c0 + t + j * 256];
        __syncthreads();

#pragma unroll 4
        for (int k = 0; k < NN_CHUNK; k++) {
            float4 kp = sk[k];
#pragma unroll
            for (int u = 0; u < 4; u++) {
                float dot = __fmul_rn(ux[u], kp.x);
                dot = fmaf(uy[u], kp.y, dot);
                dot = fmaf(uz[u], kp.z, dot);
                float d = __fadd_rn(fmaf(-2.0f, dot, u2[u]), kp.w);
                if (d < bd[u]) { bd[u] = d; bi[u] = c0 + k; }
            }
        }
    }
#pragma unroll
    for (int u = 0; u < 4; u++)
        g_idx[(size_t)b * N_ + i0 + t + u * 256] = bi[u];
}

// ---------------------------------------------------------------------------
// Fused SIMT GEMM, register-staged double buffer (LDG -> regs -> smem),
// ONE __syncthreads per k-tile:
//   Y[b,o,i] = sum_c W[o, woff+c] * X[b,c,i]  (+ P[b,o,idx[b,i]] if GATHER)
//   BN: X transformed as relu(x*bsc[c]+bbi[c]) at load
//   STATS: per-CTA deterministic (sum, sumsq) partials per output channel.
// Tile 128x128, BK=16, 256 threads, 8x8 microtile.
// ---------------------------------------------------------------------------
template <int KDIM, bool GATHER, bool BN, bool STATS, int MTOT>
__global__ void __launch_bounds__(256) gemm_kernel(
    const float* __restrict__ W, int ldw, int woff,
    const float* __restrict__ X, int N,
    const float* __restrict__ P,
    const int*   __restrict__ idx,
    const float* __restrict__ bsc,
    const float* __restrict__ bbi,
    float* __restrict__ Y,
    float* __restrict__ part)
{
    __shared__ __align__(16) float Ws[2][16][132];
    __shared__ __align__(16) float Xs[2][16][132];

    const int b   = blockIdx.z;
    const int ob0 = blockIdx.y * 128;
    const int ib0 = blockIdx.x * 128;
    const int t   = threadIdx.x;
    const int tr  = t & 15;
    const int tc  = t >> 4;

    const float* Wp = W + woff;
    const float* Xb = X + (size_t)b * KDIM * N;

    const int wc  = t & 15, wr0 = t >> 4;       // W load mapping
    const int xc  = (t & 31) * 4, xr0 = t >> 5; // X load mapping

    float  wreg[8];
    float4 xreg[2];

    auto ldg_tile = [&](int kt) {
        int k0 = kt * 16;
#pragma unroll
        for (int j = 0; j < 8; j++) {
            int r = wr0 + j * 16;
            wreg[j] = __ldg(Wp + (size_t)(ob0 + r) * ldw + k0 + wc);
        }
#pragma unroll
        for (int j = 0; j < 2; j++) {
            int kr = xr0 + j * 8;
            xreg[j] = *(const float4*)(Xb + (size_t)(k0 + kr) * N + ib0 + xc);
        }
    };
    auto st_tile = [&](int kt, int buf) {
        int k0 = kt * 16;
#pragma unroll
        for (int j = 0; j < 8; j++)
            Ws[buf][wc][wr0 + j * 16] = wreg[j];
#pragma unroll
        for (int j = 0; j < 2; j++) {
            int kr = xr0 + j * 8;
            float4 v = xreg[j];
            if (BN) {
                float s = bsc[k0 + kr], bb = bbi[k0 + kr];
                v.x = fmaxf(fmaf(v.x, s, bb), 0.f);
                v.y = fmaxf(fmaf(v.y, s, bb), 0.f);
                v.z = fmaxf(fmaf(v.z, s, bb), 0.f);
                v.w = fmaxf(fmaf(v.w, s, bb), 0.f);
            }
            *(float4*)(&Xs[buf][kr][xc]) = v;
        }
    };

    float acc[8][8];
#pragma unroll
    for (int j = 0; j < 8; j++)
#pragma unroll
        for (int i = 0; i < 8; i++) acc[j][i] = 0.f;

    constexpr int NKT = KDIM / 16;
    ldg_tile(0);
    st_tile(0, 0);
    __syncthreads();

    int buf = 0;
    for (int kt = 0; kt < NKT; ++kt) {
        if (kt + 1 < NKT) ldg_tile(kt + 1);    // gmem loads overlap compute
#pragma unroll
        for (int kk = 0; kk < 16; kk++) {
            float a[8], x[8];
            *(float4*)(a)     = *(const float4*)(&Ws[buf][kk][tc * 8]);
            *(float4*)(a + 4) = *(const float4*)(&Ws[buf][kk][tc * 8 + 4]);
            *(float4*)(x)     = *(const float4*)(&Xs[buf][kk][tr * 8]);
            *(float4*)(x + 4) = *(const float4*)(&Xs[buf][kk][tr * 8 + 4]);
#pragma unroll
            for (int j = 0; j < 8; j++)
#pragma unroll
                for (int i = 0; i < 8; i++)
                    acc[j][i] = fmaf(a[j], x[i], acc[j][i]);
        }
        if (kt + 1 < NKT) st_tile(kt + 1, buf ^ 1);
        __syncthreads();
        buf ^= 1;
    }

    if (GATHER) {
        int id[8];
#pragma unroll
        for (int i = 0; i < 8; i++)
            id[i] = idx[(size_t)b * N + ib0 + tr * 8 + i];
#pragma unroll
        for (int j = 0; j < 8; j++) {
            const float* Pr = P + ((size_t)b * MTOT + ob0 + tc * 8 + j) * M_;
#pragma unroll
            for (int i = 0; i < 8; i++)
                acc[j][i] += __ldg(&Pr[id[i]]);
        }
    }

#pragma unroll
    for (int j = 0; j < 8; j++) {
        float* Yr = Y + ((size_t)b * MTOT + ob0 + tc * 8 + j) * N + ib0 + tr * 8;
        *(float4*)(Yr)     = *(float4*)(&acc[j][0]);
        *(float4*)(Yr + 4) = *(float4*)(&acc[j][4]);
    }

    if (STATS) {
        float* sA = &Ws[0][0][0];        // 2048 floats
        float* sB = sA + 2048;           // 2048 floats (Ws block has 4224)
#pragma unroll
        for (int j = 0; j < 8; j++) {
            float a = 0.f, q = 0.f;
#pragma unroll
            for (int i = 0; i < 8; i++) {
                a += acc[j][i];
                q = fmaf(acc[j][i], acc[j][i], q);
            }
            sA[(tc * 8 + j) * 16 + tr] = a;
            sB[(tc * 8 + j) * 16 + tr] = q;
        }
        __syncthreads();
        if (t < 128) {
            float tot = 0.f;
#pragma unroll
            for (int r = 0; r < 16; r++) tot += sA[t * 16 + r];
            part[(((size_t)b * MTOT + ob0 + t) * gridDim.x + blockIdx.x) * 2 + 0] = tot;
        } else {
            int o = t - 128;
            float tot = 0.f;
#pragma unroll
            for (int r = 0; r < 16; r++) tot += sB[o * 16 + r];
            part[(((size_t)b * MTOT + ob0 + o) * gridDim.x + blockIdx.x) * 2 + 1] = tot;
        }
    }
}

// ---------------------------------------------------------------------------
// Finalize BN stats: one block per channel
// ---------------------------------------------------------------------------
template <int MTOT>
__global__ void __launch_bounds__(128) fin_kernel(
    const float* __restrict__ part,
    const float* __restrict__ gamma, const float* __restrict__ beta,
    float* __restrict__ sc, float* __restrict__ bi, float invN)
{
    const int o = blockIdx.x;
    const int t = threadIdx.x;
    float s1 = 0.f, s2 = 0.f;
    for (int b = 0; b < B_; b++) {
        const float* p = part + ((size_t)b * MTOT + o) * NT_ * 2;
        for (int q = t; q < NT_; q += 128) {
            s1 += p[q * 2 + 0];
            s2 += p[q * 2 + 1];
        }
    }
#pragma unroll
    for (int off = 16; off; off >>= 1) {
        s1 += __shfl_down_sync(0xffffffffu, s1, off);
        s2 += __shfl_down_sync(0xffffffffu, s2, off);
    }
    __shared__ float r1[4], r2[4];
    if ((t & 31) == 0) { r1[t >> 5] = s1; r2[t >> 5] = s2; }
    __syncthreads();
    if (t == 0) {
        s1 = r1[0] + r1[1] + r1[2] + r1[3];
        s2 = r2[0] + r2[1] + r2[2] + r2[3];
        float mean = s1 * invN;
        float var  = s2 * invN - mean * mean;
        float rstd = rsqrtf(var + EPS_);
        float s    = gamma[o] * rstd;
        sc[o] = s;
        bi[o] = beta[o] - mean * s;
    }
}

// ---------------------------------------------------------------------------
// Final elementwise BN+ReLU in-place on d_out
// ---------------------------------------------------------------------------
__global__ void __launch_bounds__(256) bnfin_kernel(
    float* __restrict__ Y, const float* __restrict__ sc, const float* __restrict__ bi)
{
    int row = blockIdx.y;
    int ch  = row & (H2_ - 1);
    size_t base = (size_t)row * N_;
    int i = (blockIdx.x * 256 + threadIdx.x) * 4;
    float4 v = *(float4*)(Y + base + i);
    float s = sc[ch], b = bi[ch];
    v.x = fmaxf(fmaf(v.x, s, b), 0.f);
    v.y = fmaxf(fmaf(v.y, s, b), 0.f);
    v.z = fmaxf(fmaf(v.z, s, b), 0.f);
    v.w = fmaxf(fmaf(v.w, s, b), 0.f);
    *(float4*)(Y + base + i) = v;
}

// ---------------------------------------------------------------------------
// Launch
// ---------------------------------------------------------------------------
extern "C" void kernel_launch(void* const* d_in, const int* in_sizes, int n_in,
                              void* d_out, int out_size)
{
    const float* unknown = (const float*)d_in[0];
    const float* known   = (const float*)d_in[1];
    const float* uf      = (const float*)d_in[2];
    const float* kf      = (const float*)d_in[3];
    const float* w1      = (const float*)d_in[4];
    const float* gamma1  = (const float*)d_in[5];
    const float* beta1   = (const float*)d_in[6];
    const float* w2      = (const float*)d_in[7];
    const float* gamma2  = (const float*)d_in[8];
    const float* beta2   = (const float*)d_in[9];
    float* out = (float*)d_out;

    float *pP, *ph, *pp1, *pp2, *ps1, *pb1, *ps2, *pb2;
    int* pidx;
    cudaGetSymbolAddress((void**)&pP,   g_P);
    cudaGetSymbolAddress((void**)&ph,   g_h);
    cudaGetSymbolAddress((void**)&pp1,  g_part1);
    cudaGetSymbolAddress((void**)&pp2,  g_part2);
    cudaGetSymbolAddress((void**)&ps1,  g_scale1);
    cudaGetSymbolAddress((void**)&pb1,  g_bias1);
    cudaGetSymbolAddress((void**)&ps2,  g_scale2);
    cudaGetSymbolAddress((void**)&pb2,  g_bias2);
    cudaGetSymbolAddress((void**)&pidx, g_idx);

    const float invN = 1.0f / (float)(B_ * N_);

    prep_kernel<<<(B_ * M_ + 255) / 256, 256>>>(known);

    nn_kernel<<<dim3(N_ / 1024, B_), 256>>>(unknown);

    // P = w1[:, :256] @ known_feats
    gemm_kernel<C2_, false, false, false, H1_>
        <<<dim3(M_ / 128, H1_ / 128, B_), 256>>>(
            w1, 384, 0, kf, M_, nullptr, nullptr, nullptr, nullptr, pP, nullptr);

    // h = w1[:, 256:] @ unknow_feats + gather(P, idx); stats1
    gemm_kernel<C1_, true, false, true, H1_>
        <<<dim3(N_ / 128, H1_ / 128, B_), 256>>>(
            w1, 384, C2_, uf, N_, pP, pidx, nullptr, nullptr, ph, pp1);

    fin_kernel<H1_><<<H1_, 128>>>(pp1, gamma1, beta1, ps1, pb1, invN);

    // out_pre = w2 @ relu(bn1(h)) [BN fused in loads]; stats2
    gemm_kernel<H1_, false, true, true, H2_>
        <<<dim3(N_ / 128, H2_ / 128, B_), 256>>>(
            w2, 256, 0, ph, N_, nullptr, nullptr, ps1, pb1, out, pp2);

    fin_kernel<H2_><<<H2_, 128>>>(pp2, gamma2, beta2, ps2, pb2, invN);

    // out = relu(bn2(out)) in place
    bnfin_kernel<<<dim3(N_ / 1024, B_ * H2_), 256>>>(out, ps2, pb2);
}

// round 5
// speedup vs baseline: 1.8918x; 1.2612x over previous
#include <cuda_runtime.h>
#include <cstdint>

// ---------------------------------------------------------------------------
// Problem constants
// ---------------------------------------------------------------------------
#define B_   2
#define N_   65536
#define M_   16384
#define C1_  128
#define C2_  256
#define H1_  256
#define H2_  128
#define NT_  512
#define EPS_ 1e-5f

// ---------------------------------------------------------------------------
// Scratch (device globals -- no allocation allowed)
// ---------------------------------------------------------------------------
__device__ __align__(16) float4 g_kpack[B_ * M_];
__device__ int    g_idx[B_ * N_];
__device__ float  g_P[(size_t)B_ * H1_ * M_];
__device__ float  g_h[(size_t)B_ * H1_ * N_];
__device__ float  g_part1[(size_t)B_ * H1_ * NT_ * 2];
__device__ float  g_part2[(size_t)B_ * H2_ * NT_ * 2];
__device__ float  g_scale1[H1_], g_bias1[H1_];
__device__ float  g_scale2[H2_], g_bias2[H2_];

// ---------------------------------------------------------------------------
// helpers
// ---------------------------------------------------------------------------
__device__ __forceinline__ uint32_t cvt_tf32(float f) {
    uint32_t u;
    asm("cvt.rna.tf32.f32 %0, %1;" : "=r"(u) : "f"(f));
    return u;
}
__device__ __forceinline__ void mma_tf32(float* c, const uint32_t* a,
                                         uint32_t b0, uint32_t b1) {
    asm volatile(
        "mma.sync.aligned.m16n8k8.row.col.f32.tf32.tf32.f32 "
        "{%0,%1,%2,%3}, {%4,%5,%6,%7}, {%8,%9}, {%0,%1,%2,%3};\n"
        : "+f"(c[0]), "+f"(c[1]), "+f"(c[2]), "+f"(c[3])
        : "r"(a[0]), "r"(a[1]), "r"(a[2]), "r"(a[3]), "r"(b0), "r"(b1));
}

// ---------------------------------------------------------------------------
// K0: pack known points (x, y, z, k2), k2 = (x*x + y*y) + z*z, per-op fp32
// ---------------------------------------------------------------------------
__global__ void prep_kernel(const float* __restrict__ known) {
    int j = blockIdx.x * 256 + threadIdx.x;
    if (j < B_ * M_) {
        float kx = known[3 * j + 0];
        float ky = known[3 * j + 1];
        float kz = known[3 * j + 2];
        float k2 = __fadd_rn(__fadd_rn(__fmul_rn(kx, kx), __fmul_rn(ky, ky)),
                             __fmul_rn(kz, kz));
        g_kpack[j] = make_float4(kx, ky, kz, k2);
    }
}

// ---------------------------------------------------------------------------
// K1: brute-force 1-NN, bitwise-matching reference arithmetic (unchanged).
// ---------------------------------------------------------------------------
#define NN_CHUNK 2048
__global__ void __launch_bounds__(256) nn_kernel(const float* __restrict__ unknown) {
    __shared__ __align__(16) float4 sk[NN_CHUNK];
    const int b  = blockIdx.y;
    const int i0 = blockIdx.x * 1024;
    const int t  = threadIdx.x;

    float ux[4], uy[4], uz[4], u2[4], bd[4];
    int   bi[4];
#pragma unroll
    for (int u = 0; u < 4; u++) {
        int i = i0 + t + u * 256;
        const float* up = unknown + ((size_t)b * N_ + i) * 3;
        ux[u] = up[0]; uy[u] = up[1]; uz[u] = up[2];
        u2[u] = __fadd_rn(__fadd_rn(__fmul_rn(ux[u], ux[u]), __fmul_rn(uy[u], uy[u])),
                          __fmul_rn(uz[u], uz[u]));
        bd[u] = 3.4e38f; bi[u] = 0;
    }

    const float4* gk = g_kpack + (size_t)b * M_;
    for (int c0 = 0; c0 < M_; c0 += NN_CHUNK) {
        __syncthreads();
#pragma unroll
        for (int j = 0; j < NN_CHUNK / 256; j++)
            sk[t + j * 256] = gk[c0 + t + j * 256];
        __syncthreads();

#pragma unroll 4
        for (int k = 0; k < NN_CHUNK; k++) {
            float4 kp = sk[k];
#pragma unroll
            for (int u = 0; u < 4; u++) {
                float dot = __fmul_rn(ux[u], kp.x);
                dot = fmaf(uy[u], kp.y, dot);
                dot = fmaf(uz[u], kp.z, dot);
                float d = __fadd_rn(fmaf(-2.0f, dot, u2[u]), kp.w);
                if (d < bd[u]) { bd[u] = d; bi[u] = c0 + k; }
            }
        }
    }
#pragma unroll
    for (int u = 0; u < 4; u++)
        g_idx[(size_t)b * N_ + i0 + t + u * 256] = bi[u];
}

// ---------------------------------------------------------------------------
// Tensor-core (tf32 mma.sync) fused GEMM.
//   Y[b,o,i] = sum_c W[o, woff+c] * X[b,c,i]  (+ P[b,o,idx[b,i]] if GATHER)
//   BN: X transformed as relu(x*bsc[c]+bbi[c]) at staging
//   STATS: per-CTA deterministic (sum, sumsq) partials per output channel.
// CTA tile 128(o) x 128(i), BK=32, 256 threads = 8 warps (4 o x 2 i),
// warp tile 32x64 = 2 m16 x 8 n8 fragments. Smem holds operands in
// fragment order so fetch is LDS.128.
// ---------------------------------------------------------------------------
template <int KDIM, bool GATHER, bool BN, bool STATS, int MTOT>
__global__ void __launch_bounds__(256, 2) gemm_kernel(
    const float* __restrict__ W, int ldw, int woff,
    const float* __restrict__ X, int N,
    const float* __restrict__ P,
    const int*   __restrict__ idx,
    const float* __restrict__ bsc,
    const float* __restrict__ bbi,
    float* __restrict__ Y,
    float* __restrict__ part)
{
    // fragment-ordered operand buffers: [s:4][tile:8][lane:32][4]
    __shared__ __align__(16) uint32_t As[4096];
    __shared__ __align__(16) uint32_t Bs[4096];

    const int b   = blockIdx.z;
    const int ob0 = blockIdx.y * 128;
    const int ib0 = blockIdx.x * 128;
    const int t   = threadIdx.x;
    const int lane = t & 31, wid = t >> 5;
    const int wo = wid >> 1, wn = wid & 1;       // warp grid 4(o) x 2(i)
    const int gid = lane >> 2, tig = lane & 3;

    const float* Wp = W + woff;
    const float* Xb = X + (size_t)b * KDIM * N;

    float acc[2][8][4];                          // [m16 tile][n8 tile][c0..c3]
#pragma unroll
    for (int m = 0; m < 2; m++)
#pragma unroll
        for (int n = 0; n < 8; n++)
#pragma unroll
            for (int e = 0; e < 4; e++) acc[m][n][e] = 0.f;

    // staging index precompute
    const int w_o   = t >> 1;                    // 0..127
    const int w_kq0 = (t & 1) * 16;              // 0 or 16
    const int w_mt  = w_o >> 4, w_gid = w_o & 7, w_hi = (w_o >> 3) & 1;

    const int x_k   = t >> 3;                    // 0..31
    const int x_i0  = (t & 7) * 16;              // 0..112
    const int x_s   = x_k >> 3;
    const int x_tig = x_k & 3, x_hi = (x_k >> 2) & 1;

    constexpr int NKT = KDIM / 32;
    for (int kt = 0; kt < NKT; ++kt) {
        const int k0 = kt * 32;
        if (kt > 0) __syncthreads();             // compute done reading smem

        // ---- stage W tile (128 x 32) into fragment order ----
        {
            const float* wr = Wp + (size_t)(ob0 + w_o) * ldw + k0 + w_kq0;
#pragma unroll
            for (int j = 0; j < 4; j++) {
                float4 v = *(const float4*)(wr + j * 4);
                uint32_t q[4] = {cvt_tf32(v.x), cvt_tf32(v.y), cvt_tf32(v.z), cvt_tf32(v.w)};
#pragma unroll
                for (int e = 0; e < 4; e++) {
                    int kk = w_kq0 + j * 4 + e;
                    int s = kk >> 3, c = kk & 7;
                    As[(((s * 8 + w_mt) * 32 + w_gid * 4 + (c & 3)) << 2)
                       + w_hi + ((c >> 2) << 1)] = q[e];
                }
            }
        }
        // ---- stage X tile (32 x 128) into fragment order (+BN) ----
        {
            const float* xr = Xb + (size_t)(k0 + x_k) * N + ib0 + x_i0;
            float bs = 0.f, bb = 0.f;
            if (BN) { bs = bsc[k0 + x_k]; bb = bbi[k0 + x_k]; }
#pragma unroll
            for (int j = 0; j < 4; j++) {
                float4 v = *(const float4*)(xr + j * 4);
                if (BN) {
                    v.x = fmaxf(fmaf(v.x, bs, bb), 0.f);
                    v.y = fmaxf(fmaf(v.y, bs, bb), 0.f);
                    v.z = fmaxf(fmaf(v.z, bs, bb), 0.f);
                    v.w = fmaxf(fmaf(v.w, bs, bb), 0.f);
                }
                uint32_t q[4] = {cvt_tf32(v.x), cvt_tf32(v.y), cvt_tf32(v.z), cvt_tf32(v.w)};
#pragma unroll
                for (int e = 0; e < 4; e++) {
                    int i = x_i0 + j * 4 + e;
                    int nt = i >> 3, gg = i & 7;
                    Bs[(((x_s * 8 + (nt >> 1)) * 32 + gg * 4 + x_tig) << 2)
                       + (nt & 1) * 2 + x_hi] = q[e];
                }
            }
        }
        __syncthreads();

        // ---- compute: 4 k8 slices x (2 m-tiles x 8 n-tiles) mma ----
#pragma unroll
        for (int s = 0; s < 4; s++) {
            uint4 af[2];
            af[0] = *(const uint4*)&As[((s * 8 + wo * 2 + 0) * 32 + lane) << 2];
            af[1] = *(const uint4*)&As[((s * 8 + wo * 2 + 1) * 32 + lane) << 2];
            uint4 bf[4];
#pragma unroll
            for (int p = 0; p < 4; p++)
                bf[p] = *(const uint4*)&Bs[((s * 8 + wn * 4 + p) * 32 + lane) << 2];
#pragma unroll
            for (int m = 0; m < 2; m++)
#pragma unroll
                for (int p = 0; p < 4; p++) {
                    mma_tf32(acc[m][2 * p],     (const uint32_t*)&af[m], bf[p].x, bf[p].y);
                    mma_tf32(acc[m][2 * p + 1], (const uint32_t*)&af[m], bf[p].z, bf[p].w);
                }
        }
    }

    const int o_base = ob0 + wo * 32;
    const int i_base = ib0 + wn * 64;

    if (GATHER) {
        int2 id[8];
#pragma unroll
        for (int n = 0; n < 8; n++)
            id[n] = *(const int2*)(idx + (size_t)b * N + i_base + n * 8 + tig * 2);
#pragma unroll
        for (int m = 0; m < 2; m++) {
            const float* Pr0 = P + ((size_t)b * MTOT + o_base + m * 16 + gid) * M_;
            const float* Pr8 = Pr0 + (size_t)8 * M_;
#pragma unroll
            for (int n = 0; n < 8; n++) {
                acc[m][n][0] += __ldg(&Pr0[id[n].x]);
                acc[m][n][1] += __ldg(&Pr0[id[n].y]);
                acc[m][n][2] += __ldg(&Pr8[id[n].x]);
                acc[m][n][3] += __ldg(&Pr8[id[n].y]);
            }
        }
    }

    // ---- store output (2 floats per fragment row) ----
#pragma unroll
    for (int m = 0; m < 2; m++) {
        float* Y0 = Y + ((size_t)b * MTOT + o_base + m * 16 + gid) * N + i_base + tig * 2;
        float* Y8 = Y0 + (size_t)8 * N;
#pragma unroll
        for (int n = 0; n < 8; n++) {
            *(float2*)(Y0 + n * 8) = make_float2(acc[m][n][0], acc[m][n][1]);
            *(float2*)(Y8 + n * 8) = make_float2(acc[m][n][2], acc[m][n][3]);
        }
    }

    if (STATS) {
        // per-thread row sums (deterministic fixed order), quad butterfly,
        // then cross-warp combine in smem (reuse As).
        float s1[2][2], s2[2][2];
#pragma unroll
        for (int m = 0; m < 2; m++) {
            float a0 = 0.f, q0 = 0.f, a1 = 0.f, q1 = 0.f;
#pragma unroll
            for (int n = 0; n < 8; n++) {
                a0 += acc[m][n][0]; q0 = fmaf(acc[m][n][0], acc[m][n][0], q0);
                a0 += acc[m][n][1]; q0 = fmaf(acc[m][n][1], acc[m][n][1], q0);
                a1 += acc[m][n][2]; q1 = fmaf(acc[m][n][2], acc[m][n][2], q1);
                a1 += acc[m][n][3]; q1 = fmaf(acc[m][n][3], acc[m][n][3], q1);
            }
            s1[m][0] = a0; s2[m][0] = q0; s1[m][1] = a1; s2[m][1] = q1;
        }
#pragma unroll
        for (int m = 0; m < 2; m++)
#pragma unroll
            for (int h = 0; h < 2; h++) {
#pragma unroll
                for (int off = 1; off <= 2; off <<= 1) {
                    s1[m][h] += __shfl_xor_sync(0xffffffffu, s1[m][h], off);
                    s2[m][h] += __shfl_xor_sync(0xffffffffu, s2[m][h], off);
                }
            }
        float* sb1 = (float*)As;            // [2 wn][128 o]
        float* sb2 = sb1 + 256;
        __syncthreads();
        if (tig == 0) {
#pragma unroll
            for (int m = 0; m < 2; m++)
#pragma unroll
                for (int h = 0; h < 2; h++) {
                    int ol = wo * 32 + m * 16 + h * 8 + gid;
                    sb1[wn * 128 + ol] = s1[m][h];
                    sb2[wn * 128 + ol] = s2[m][h];
                }
        }
        __syncthreads();
        if (t < 128) {
            float tot = sb1[t] + sb1[128 + t];
            part[(((size_t)b * MTOT + ob0 + t) * gridDim.x + blockIdx.x) * 2 + 0] = tot;
        } else {
            int o = t - 128;
            float tot = sb2[o] + sb2[128 + o];
            part[(((size_t)b * MTOT + ob0 + o) * gridDim.x + blockIdx.x) * 2 + 1] = tot;
        }
    }
}

// ---------------------------------------------------------------------------
// Finalize BN stats: one block per channel
// ---------------------------------------------------------------------------
template <int MTOT>
__global__ void __launch_bounds__(128) fin_kernel(
    const float* __restrict__ part,
    const float* __restrict__ gamma, const float* __restrict__ beta,
    float* __restrict__ sc, float* __restrict__ bi, float invN)
{
    const int o = blockIdx.x;
    const int t = threadIdx.x;
    float s1 = 0.f, s2 = 0.f;
    for (int b = 0; b < B_; b++) {
        const float* p = part + ((size_t)b * MTOT + o) * NT_ * 2;
        for (int q = t; q < NT_; q += 128) {
            s1 += p[q * 2 + 0];
            s2 += p[q * 2 + 1];
        }
    }
#pragma unroll
    for (int off = 16; off; off >>= 1) {
        s1 += __shfl_down_sync(0xffffffffu, s1, off);
        s2 += __shfl_down_sync(0xffffffffu, s2, off);
    }
    __shared__ float r1[4], r2[4];
    if ((t & 31) == 0) { r1[t >> 5] = s1; r2[t >> 5] = s2; }
    __syncthreads();
    if (t == 0) {
        s1 = r1[0] + r1[1] + r1[2] + r1[3];
        s2 = r2[0] + r2[1] + r2[2] + r2[3];
        float mean = s1 * invN;
        float var  = s2 * invN - mean * mean;
        float rstd = rsqrtf(var + EPS_);
        float s    = gamma[o] * rstd;
        sc[o] = s;
        bi[o] = beta[o] - mean * s;
    }
}

// ---------------------------------------------------------------------------
// Final elementwise BN+ReLU in-place on d_out
// ---------------------------------------------------------------------------
__global__ void __launch_bounds__(256) bnfin_kernel(
    float* __restrict__ Y, const float* __restrict__ sc, const float* __restrict__ bi)
{
    int row = blockIdx.y;
    int ch  = row & (H2_ - 1);
    size_t base = (size_t)row * N_;
    int i = (blockIdx.x * 256 + threadIdx.x) * 4;
    float4 v = *(float4*)(Y + base + i);
    float s = sc[ch], b = bi[ch];
    v.x = fmaxf(fmaf(v.x, s, b), 0.f);
    v.y = fmaxf(fmaf(v.y, s, b), 0.f);
    v.z = fmaxf(fmaf(v.z, s, b), 0.f);
    v.w = fmaxf(fmaf(v.w, s, b), 0.f);
    *(float4*)(Y + base + i) = v;
}

// ---------------------------------------------------------------------------
// Launch
// ---------------------------------------------------------------------------
extern "C" void kernel_launch(void* const* d_in, const int* in_sizes, int n_in,
                              void* d_out, int out_size)
{
    const float* unknown = (const float*)d_in[0];
    const float* known   = (const float*)d_in[1];
    const float* uf      = (const float*)d_in[2];
    const float* kf      = (const float*)d_in[3];
    const float* w1      = (const float*)d_in[4];
    const float* gamma1  = (const float*)d_in[5];
    const float* beta1   = (const float*)d_in[6];
    const float* w2      = (const float*)d_in[7];
    const float* gamma2  = (const float*)d_in[8];
    const float* beta2   = (const float*)d_in[9];
    float* out = (float*)d_out;

    float *pP, *ph, *pp1, *pp2, *ps1, *pb1, *ps2, *pb2;
    int* pidx;
    cudaGetSymbolAddress((void**)&pP,   g_P);
    cudaGetSymbolAddress((void**)&ph,   g_h);
    cudaGetSymbolAddress((void**)&pp1,  g_part1);
    cudaGetSymbolAddress((void**)&pp2,  g_part2);
    cudaGetSymbolAddress((void**)&ps1,  g_scale1);
    cudaGetSymbolAddress((void**)&pb1,  g_bias1);
    cudaGetSymbolAddress((void**)&ps2,  g_scale2);
    cudaGetSymbolAddress((void**)&pb2,  g_bias2);
    cudaGetSymbolAddress((void**)&pidx, g_idx);

    const float invN = 1.0f / (float)(B_ * N_);

    prep_kernel<<<(B_ * M_ + 255) / 256, 256>>>(known);

    nn_kernel<<<dim3(N_ / 1024, B_), 256>>>(unknown);

    // P = w1[:, :256] @ known_feats
    gemm_kernel<C2_, false, false, false, H1_>
        <<<dim3(M_ / 128, H1_ / 128, B_), 256>>>(
            w1, 384, 0, kf, M_, nullptr, nullptr, nullptr, nullptr, pP, nullptr);

    // h = w1[:, 256:] @ unknow_feats + gather(P, idx); stats1
    gemm_kernel<C1_, true, false, true, H1_>
        <<<dim3(N_ / 128, H1_ / 128, B_), 256>>>(
            w1, 384, C2_, uf, N_, pP, pidx, nullptr, nullptr, ph, pp1);

    fin_kernel<H1_><<<H1_, 128>>>(pp1, gamma1, beta1, ps1, pb1, invN);

    // out_pre = w2 @ relu(bn1(h)) [BN fused in staging]; stats2
    gemm_kernel<H1_, false, true, true, H2_>
        <<<dim3(N_ / 128, H2_ / 128, B_), 256>>>(
            w2, 256, 0, ph, N_, nullptr, nullptr, ps1, pb1, out, pp2);

    fin_kernel<H2_><<<H2_, 128>>>(pp2, gamma2, beta2, ps2, pb2, invN);

    // out = relu(bn2(out)) in place
    bnfin_kernel<<<dim3(N_ / 1024, B_ * H2_), 256>>>(out, ps2, pb2);
}

// round 6
// speedup vs baseline: 1.8974x; 1.0029x over previous
#include <cuda_runtime.h>
#include <cstdint>

// ---------------------------------------------------------------------------
// Problem constants
// ---------------------------------------------------------------------------
#define B_   2
#define N_   65536
#define M_   16384
#define C1_  128
#define C2_  256
#define H1_  256
#define H2_  128
#define NT_  512
#define EPS_ 1e-5f

// ---------------------------------------------------------------------------
// Scratch (device globals -- no allocation allowed)
// ---------------------------------------------------------------------------
__device__ __align__(16) float4 g_kpack[B_ * M_];
__device__ int    g_idx[B_ * N_];
__device__ float  g_P[(size_t)B_ * H1_ * M_];
__device__ float  g_h[(size_t)B_ * H1_ * N_];
__device__ float  g_part1[(size_t)B_ * H1_ * NT_ * 2];
__device__ float  g_part2[(size_t)B_ * H2_ * NT_ * 2];
__device__ float  g_scale1[H1_], g_bias1[H1_];
__device__ float  g_scale2[H2_], g_bias2[H2_];

// ---------------------------------------------------------------------------
// helpers
// ---------------------------------------------------------------------------
__device__ __forceinline__ uint32_t cvt_tf32(float f) {
    uint32_t u;
    asm("cvt.rna.tf32.f32 %0, %1;" : "=r"(u) : "f"(f));
    return u;
}
__device__ __forceinline__ void mma_tf32(float* c, const uint32_t* a,
                                         uint32_t b0, uint32_t b1) {
    asm volatile(
        "mma.sync.aligned.m16n8k8.row.col.f32.tf32.tf32.f32 "
        "{%0,%1,%2,%3}, {%4,%5,%6,%7}, {%8,%9}, {%0,%1,%2,%3};\n"
        : "+f"(c[0]), "+f"(c[1]), "+f"(c[2]), "+f"(c[3])
        : "r"(a[0]), "r"(a[1]), "r"(a[2]), "r"(a[3]), "r"(b0), "r"(b1));
}

// ---------------------------------------------------------------------------
// K0: pack known points (x, y, z, k2), k2 = (x*x + y*y) + z*z, per-op fp32
// ---------------------------------------------------------------------------
__global__ void prep_kernel(const float* __restrict__ known) {
    int j = blockIdx.x * 256 + threadIdx.x;
    if (j < B_ * M_) {
        float kx = known[3 * j + 0];
        float ky = known[3 * j + 1];
        float kz = known[3 * j + 2];
        float k2 = __fadd_rn(__fadd_rn(__fmul_rn(kx, kx), __fmul_rn(ky, ky)),
                             __fmul_rn(kz, kz));
        g_kpack[j] = make_float4(kx, ky, kz, k2);
    }
}

// ---------------------------------------------------------------------------
// K1: brute-force 1-NN, bitwise-matching reference arithmetic (unchanged).
// ---------------------------------------------------------------------------
#define NN_CHUNK 2048
__global__ void __launch_bounds__(256) nn_kernel(const float* __restrict__ unknown) {
    __shared__ __align__(16) float4 sk[NN_CHUNK];
    const int b  = blockIdx.y;
    const int i0 = blockIdx.x * 1024;
    const int t  = threadIdx.x;

    float ux[4], uy[4], uz[4], u2[4], bd[4];
    int   bi[4];
#pragma unroll
    for (int u = 0; u < 4; u++) {
        int i = i0 + t + u * 256;
        const float* up = unknown + ((size_t)b * N_ + i) * 3;
        ux[u] = up[0]; uy[u] = up[1]; uz[u] = up[2];
        u2[u] = __fadd_rn(__fadd_rn(__fmul_rn(ux[u], ux[u]), __fmul_rn(uy[u], uy[u])),
                          __fmul_rn(uz[u], uz[u]));
        bd[u] = 3.4e38f; bi[u] = 0;
    }

    const float4* gk = g_kpack + (size_t)b * M_;
    for (int c0 = 0; c0 < M_; c0 += NN_CHUNK) {
        __syncthreads();
#pragma unroll
        for (int j = 0; j < NN_CHUNK / 256; j++)
            sk[t + j * 256] = gk[c0 + t + j * 256];
        __syncthreads();

#pragma unroll 4
        for (int k = 0; k < NN_CHUNK; k++) {
            float4 kp = sk[k];
#pragma unroll
            for (int u = 0; u < 4; u++) {
                float dot = __fmul_rn(ux[u], kp.x);
                dot = fmaf(uy[u], kp.y, dot);
                dot = fmaf(uz[u], kp.z, dot);
                float d = __fadd_rn(fmaf(-2.0f, dot, u2[u]), kp.w);
                if (d < bd[u]) { bd[u] = d; bi[u] = c0 + k; }
            }
        }
    }
#pragma unroll
    for (int u = 0; u < 4; u++)
        g_idx[(size_t)b * N_ + i0 + t + u * 256] = bi[u];
}

// ---------------------------------------------------------------------------
// Tensor-core (tf32 mma.sync) fused GEMM, DOUBLE-BUFFERED staging.
//   Y[b,o,i] = sum_c W[o, woff+c] * X[b,c,i]  (+ P[b,o,idx[b,i]] if GATHER)
//   BN: X transformed as relu(x*bsc[c]+bbi[c]) at staging
//   STATS: per-CTA deterministic (sum, sumsq) partials per output channel.
// CTA tile 128(o) x 128(i), BK=32, 256 threads = 8 warps (4 o x 2 i),
// warp tile 32x64 = 2 m16 x 8 n8 fragments. Smem in fragment order.
// ONE barrier per k-tile: stage(kt,buf) -> sync -> compute(kt,buf).
// Overwrite of buf at stage(kt) is ordered after the reads in compute(kt-2)
// because every warp passes sync(kt-1) (which follows its compute(kt-2)).
// ---------------------------------------------------------------------------
template <int KDIM, bool GATHER, bool BN, bool STATS, int MTOT>
__global__ void __launch_bounds__(256, 2) gemm_kernel(
    const float* __restrict__ W, int ldw, int woff,
    const float* __restrict__ X, int N,
    const float* __restrict__ P,
    const int*   __restrict__ idx,
    const float* __restrict__ bsc,
    const float* __restrict__ bbi,
    float* __restrict__ Y,
    float* __restrict__ part)
{
    // fragment-ordered operand buffers: [buf:2][s:4][tile:8][lane:32][4]
    __shared__ __align__(16) uint32_t As[2][4096];
    __shared__ __align__(16) uint32_t Bs[2][4096];

    const int b   = blockIdx.z;
    const int ob0 = blockIdx.y * 128;
    const int ib0 = blockIdx.x * 128;
    const int t   = threadIdx.x;
    const int lane = t & 31, wid = t >> 5;
    const int wo = wid >> 1, wn = wid & 1;       // warp grid 4(o) x 2(i)
    const int gid = lane >> 2, tig = lane & 3;

    const float* Wp = W + woff;
    const float* Xb = X + (size_t)b * KDIM * N;

    float acc[2][8][4];
#pragma unroll
    for (int m = 0; m < 2; m++)
#pragma unroll
        for (int n = 0; n < 8; n++)
#pragma unroll
            for (int e = 0; e < 4; e++) acc[m][n][e] = 0.f;

    // staging index precompute
    const int w_o   = t >> 1;                    // 0..127
    const int w_kq0 = (t & 1) * 16;              // 0 or 16
    const int w_mt  = w_o >> 4, w_gid = w_o & 7, w_hi = (w_o >> 3) & 1;

    const int x_k   = t >> 3;                    // 0..31
    const int x_i0  = (t & 7) * 16;              // 0..112
    const int x_s   = x_k >> 3;
    const int x_tig = x_k & 3, x_hi = (x_k >> 2) & 1;

    constexpr int NKT = KDIM / 32;
    int buf = 0;
    for (int kt = 0; kt < NKT; ++kt) {
        const int k0 = kt * 32;
        uint32_t* Ab = As[buf];
        uint32_t* Bb = Bs[buf];

        // ---- stage W tile (128 x 32) into fragment order ----
        {
            const float* wr = Wp + (size_t)(ob0 + w_o) * ldw + k0 + w_kq0;
#pragma unroll
            for (int j = 0; j < 4; j++) {
                float4 v = *(const float4*)(wr + j * 4);
                uint32_t q[4] = {cvt_tf32(v.x), cvt_tf32(v.y), cvt_tf32(v.z), cvt_tf32(v.w)};
#pragma unroll
                for (int e = 0; e < 4; e++) {
                    int kk = w_kq0 + j * 4 + e;
                    int s = kk >> 3, c = kk & 7;
                    Ab[(((s * 8 + w_mt) * 32 + w_gid * 4 + (c & 3)) << 2)
                       + w_hi + ((c >> 2) << 1)] = q[e];
                }
            }
        }
        // ---- stage X tile (32 x 128) into fragment order (+BN) ----
        {
            const float* xr = Xb + (size_t)(k0 + x_k) * N + ib0 + x_i0;
            float bs = 0.f, bb = 0.f;
            if (BN) { bs = bsc[k0 + x_k]; bb = bbi[k0 + x_k]; }
#pragma unroll
            for (int j = 0; j < 4; j++) {
                float4 v = *(const float4*)(xr + j * 4);
                if (BN) {
                    v.x = fmaxf(fmaf(v.x, bs, bb), 0.f);
                    v.y = fmaxf(fmaf(v.y, bs, bb), 0.f);
                    v.z = fmaxf(fmaf(v.z, bs, bb), 0.f);
                    v.w = fmaxf(fmaf(v.w, bs, bb), 0.f);
                }
                uint32_t q[4] = {cvt_tf32(v.x), cvt_tf32(v.y), cvt_tf32(v.z), cvt_tf32(v.w)};
#pragma unroll
                for (int e = 0; e < 4; e++) {
                    int i = x_i0 + j * 4 + e;
                    int nt = i >> 3, gg = i & 7;
                    Bb[(((x_s * 8 + (nt >> 1)) * 32 + gg * 4 + x_tig) << 2)
                       + (nt & 1) * 2 + x_hi] = q[e];
                }
            }
        }
        __syncthreads();

        // ---- compute: 4 k8 slices x (2 m-tiles x 8 n-tiles) mma ----
#pragma unroll
        for (int s = 0; s < 4; s++) {
            uint4 af[2];
            af[0] = *(const uint4*)&Ab[((s * 8 + wo * 2 + 0) * 32 + lane) << 2];
            af[1] = *(const uint4*)&Ab[((s * 8 + wo * 2 + 1) * 32 + lane) << 2];
            uint4 bf[4];
#pragma unroll
            for (int p = 0; p < 4; p++)
                bf[p] = *(const uint4*)&Bb[((s * 8 + wn * 4 + p) * 32 + lane) << 2];
#pragma unroll
            for (int m = 0; m < 2; m++)
#pragma unroll
                for (int p = 0; p < 4; p++) {
                    mma_tf32(acc[m][2 * p],     (const uint32_t*)&af[m], bf[p].x, bf[p].y);
                    mma_tf32(acc[m][2 * p + 1], (const uint32_t*)&af[m], bf[p].z, bf[p].w);
                }
        }
        buf ^= 1;   // no barrier here: see safety argument above
    }

    const int o_base = ob0 + wo * 32;
    const int i_base = ib0 + wn * 64;

    if (GATHER) {
        int2 id[8];
#pragma unroll
        for (int n = 0; n < 8; n++)
            id[n] = *(const int2*)(idx + (size_t)b * N + i_base + n * 8 + tig * 2);
#pragma unroll
        for (int m = 0; m < 2; m++) {
            const float* Pr0 = P + ((size_t)b * MTOT + o_base + m * 16 + gid) * M_;
            const float* Pr8 = Pr0 + (size_t)8 * M_;
#pragma unroll
            for (int n = 0; n < 8; n++) {
                acc[m][n][0] += __ldg(&Pr0[id[n].x]);
                acc[m][n][1] += __ldg(&Pr0[id[n].y]);
                acc[m][n][2] += __ldg(&Pr8[id[n].x]);
                acc[m][n][3] += __ldg(&Pr8[id[n].y]);
            }
        }
    }

    // ---- store output (2 floats per fragment row) ----
#pragma unroll
    for (int m = 0; m < 2; m++) {
        float* Y0 = Y + ((size_t)b * MTOT + o_base + m * 16 + gid) * N + i_base + tig * 2;
        float* Y8 = Y0 + (size_t)8 * N;
#pragma unroll
        for (int n = 0; n < 8; n++) {
            *(float2*)(Y0 + n * 8) = make_float2(acc[m][n][0], acc[m][n][1]);
            *(float2*)(Y8 + n * 8) = make_float2(acc[m][n][2], acc[m][n][3]);
        }
    }

    if (STATS) {
        float s1[2][2], s2[2][2];
#pragma unroll
        for (int m = 0; m < 2; m++) {
            float a0 = 0.f, q0 = 0.f, a1 = 0.f, q1 = 0.f;
#pragma unroll
            for (int n = 0; n < 8; n++) {
                a0 += acc[m][n][0]; q0 = fmaf(acc[m][n][0], acc[m][n][0], q0);
                a0 += acc[m][n][1]; q0 = fmaf(acc[m][n][1], acc[m][n][1], q0);
                a1 += acc[m][n][2]; q1 = fmaf(acc[m][n][2], acc[m][n][2], q1);
                a1 += acc[m][n][3]; q1 = fmaf(acc[m][n][3], acc[m][n][3], q1);
            }
            s1[m][0] = a0; s2[m][0] = q0; s1[m][1] = a1; s2[m][1] = q1;
        }
#pragma unroll
        for (int m = 0; m < 2; m++)
#pragma unroll
            for (int h = 0; h < 2; h++) {
#pragma unroll
                for (int off = 1; off <= 2; off <<= 1) {
                    s1[m][h] += __shfl_xor_sync(0xffffffffu, s1[m][h], off);
                    s2[m][h] += __shfl_xor_sync(0xffffffffu, s2[m][h], off);
                }
            }
        float* sb1 = (float*)&As[0][0];     // [2 wn][128 o]
        float* sb2 = sb1 + 256;
        __syncthreads();                     // all compute reads of As done
        if (tig == 0) {
#pragma unroll
            for (int m = 0; m < 2; m++)
#pragma unroll
                for (int h = 0; h < 2; h++) {
                    int ol = wo * 32 + m * 16 + h * 8 + gid;
                    sb1[wn * 128 + ol] = s1[m][h];
                    sb2[wn * 128 + ol] = s2[m][h];
                }
        }
        __syncthreads();
        if (t < 128) {
            float tot = sb1[t] + sb1[128 + t];
            part[(((size_t)b * MTOT + ob0 + t) * gridDim.x + blockIdx.x) * 2 + 0] = tot;
        } else {
            int o = t - 128;
            float tot = sb2[o] + sb2[128 + o];
            part[(((size_t)b * MTOT + ob0 + o) * gridDim.x + blockIdx.x) * 2 + 1] = tot;
        }
    }
}

// ---------------------------------------------------------------------------
// Finalize BN stats: one block per channel
// ---------------------------------------------------------------------------
template <int MTOT>
__global__ void __launch_bounds__(128) fin_kernel(
    const float* __restrict__ part,
    const float* __restrict__ gamma, const float* __restrict__ beta,
    float* __restrict__ sc, float* __restrict__ bi, float invN)
{
    const int o = blockIdx.x;
    const int t = threadIdx.x;
    float s1 = 0.f, s2 = 0.f;
    for (int b = 0; b < B_; b++) {
        const float* p = part + ((size_t)b * MTOT + o) * NT_ * 2;
        for (int q = t; q < NT_; q += 128) {
            s1 += p[q * 2 + 0];
            s2 += p[q * 2 + 1];
        }
    }
#pragma unroll
    for (int off = 16; off; off >>= 1) {
        s1 += __shfl_down_sync(0xffffffffu, s1, off);
        s2 += __shfl_down_sync(0xffffffffu, s2, off);
    }
    __shared__ float r1[4], r2[4];
    if ((t & 31) == 0) { r1[t >> 5] = s1; r2[t >> 5] = s2; }
    __syncthreads();
    if (t == 0) {
        s1 = r1[0] + r1[1] + r1[2] + r1[3];
        s2 = r2[0] + r2[1] + r2[2] + r2[3];
        float mean = s1 * invN;
        float var  = s2 * invN - mean * mean;
        float rstd = rsqrtf(var + EPS_);
        float s    = gamma[o] * rstd;
        sc[o] = s;
        bi[o] = beta[o] - mean * s;
    }
}

// ---------------------------------------------------------------------------
// Final elementwise BN+ReLU in-place on d_out
// ---------------------------------------------------------------------------
__global__ void __launch_bounds__(256) bnfin_kernel(
    float* __restrict__ Y, const float* __restrict__ sc, const float* __restrict__ bi)
{
    int row = blockIdx.y;
    int ch  = row & (H2_ - 1);
    size_t base = (size_t)row * N_;
    int i = (blockIdx.x * 256 + threadIdx.x) * 4;
    float4 v = *(float4*)(Y + base + i);
    float s = sc[ch], b = bi[ch];
    v.x = fmaxf(fmaf(v.x, s, b), 0.f);
    v.y = fmaxf(fmaf(v.y, s, b), 0.f);
    v.z = fmaxf(fmaf(v.z, s, b), 0.f);
    v.w = fmaxf(fmaf(v.w, s, b), 0.f);
    *(float4*)(Y + base + i) = v;
}

// ---------------------------------------------------------------------------
// Launch
// ---------------------------------------------------------------------------
extern "C" void kernel_launch(void* const* d_in, const int* in_sizes, int n_in,
                              void* d_out, int out_size)
{
    const float* unknown = (const float*)d_in[0];
    const float* known   = (const float*)d_in[1];
    const float* uf      = (const float*)d_in[2];
    const float* kf      = (const float*)d_in[3];
    const float* w1      = (const float*)d_in[4];
    const float* gamma1  = (const float*)d_in[5];
    const float* beta1   = (const float*)d_in[6];
    const float* w2      = (const float*)d_in[7];
    const float* gamma2  = (const float*)d_in[8];
    const float* beta2   = (const float*)d_in[9];
    float* out = (float*)d_out;

    float *pP, *ph, *pp1, *pp2, *ps1, *pb1, *ps2, *pb2;
    int* pidx;
    cudaGetSymbolAddress((void**)&pP,   g_P);
    cudaGetSymbolAddress((void**)&ph,   g_h);
    cudaGetSymbolAddress((void**)&pp1,  g_part1);
    cudaGetSymbolAddress((void**)&pp2,  g_part2);
    cudaGetSymbolAddress((void**)&ps1,  g_scale1);
    cudaGetSymbolAddress((void**)&pb1,  g_bias1);
    cudaGetSymbolAddress((void**)&ps2,  g_scale2);
    cudaGetSymbolAddress((void**)&pb2,  g_bias2);
    cudaGetSymbolAddress((void**)&pidx, g_idx);

    const float invN = 1.0f / (float)(B_ * N_);

    prep_kernel<<<(B_ * M_ + 255) / 256, 256>>>(known);

    nn_kernel<<<dim3(N_ / 1024, B_), 256>>>(unknown);

    // P = w1[:, :256] @ known_feats
    gemm_kernel<C2_, false, false, false, H1_>
        <<<dim3(M_ / 128, H1_ / 128, B_), 256>>>(
            w1, 384, 0, kf, M_, nullptr, nullptr, nullptr, nullptr, pP, nullptr);

    // h = w1[:, 256:] @ unknow_feats + gather(P, idx); stats1
    gemm_kernel<C1_, true, false, true, H1_>
        <<<dim3(N_ / 128, H1_ / 128, B_), 256>>>(
            w1, 384, C2_, uf, N_, pP, pidx, nullptr, nullptr, ph, pp1);

    fin_kernel<H1_><<<H1_, 128>>>(pp1, gamma1, beta1, ps1, pb1, invN);

    // out_pre = w2 @ relu(bn1(h)) [BN fused in staging]; stats2
    gemm_kernel<H1_, false, true, true, H2_>
        <<<dim3(N_ / 128, H2_ / 128, B_), 256>>>(
            w2, 256, 0, ph, N_, nullptr, nullptr, ps1, pb1, out, pp2);

    fin_kernel<H2_><<<H2_, 128>>>(pp2, gamma2, beta2, ps2, pb2, invN);

    // out = relu(bn2(out)) in place
    bnfin_kernel<<<dim3(N_ / 1024, B_ * H2_), 256>>>(out, ps2, pb2);
}

// round 7
// speedup vs baseline: 2.1372x; 1.1264x over previous
#include <cuda_runtime.h>
#include <cstdint>

// ---------------------------------------------------------------------------
// Problem constants
// ---------------------------------------------------------------------------
#define B_   2
#define N_   65536
#define M_   16384
#define C1_  128
#define C2_  256
#define H1_  256
#define H2_  128
#define NT_  512
#define EPS_ 1e-5f

// ---------------------------------------------------------------------------
// Scratch (device globals -- no allocation allowed)
// ---------------------------------------------------------------------------
__device__ float  g_kx[B_ * M_], g_ky[B_ * M_], g_kz[B_ * M_], g_k2[B_ * M_];
__device__ int    g_idx[B_ * N_];
__device__ float  g_P[(size_t)B_ * M_ * H1_];      // TRANSPOSED: [b][m][o]
__device__ float  g_h[(size_t)B_ * H1_ * N_];
__device__ float  g_part1[(size_t)B_ * H1_ * NT_ * 2];
__device__ float  g_part2[(size_t)B_ * H2_ * NT_ * 2];
__device__ float  g_scale1[H1_], g_bias1[H1_];
__device__ float  g_scale2[H2_], g_bias2[H2_];

// ---------------------------------------------------------------------------
// helpers
// ---------------------------------------------------------------------------
__device__ __forceinline__ uint32_t cvt_tf32(float f) {
    uint32_t u;
    asm("cvt.rna.tf32.f32 %0, %1;" : "=r"(u) : "f"(f));
    return u;
}
__device__ __forceinline__ void mma_tf32(float* c, const uint32_t* a,
                                         uint32_t b0, uint32_t b1) {
    asm volatile(
        "mma.sync.aligned.m16n8k8.row.col.f32.tf32.tf32.f32 "
        "{%0,%1,%2,%3}, {%4,%5,%6,%7}, {%8,%9}, {%0,%1,%2,%3};\n"
        : "+f"(c[0]), "+f"(c[1]), "+f"(c[2]), "+f"(c[3])
        : "r"(a[0]), "r"(a[1]), "r"(a[2]), "r"(a[3]), "r"(b0), "r"(b1));
}
// packed f32x2 (both lanes = independent fp32 RN ops, bitwise == scalar)
__device__ __forceinline__ uint64_t pk2(float x, float y) {
    uint64_t r;
    asm("mov.b64 %0, {%1, %2};" : "=l"(r) : "f"(x), "f"(y));
    return r;
}
__device__ __forceinline__ void upk2(float& lo, float& hi, uint64_t v) {
    asm("mov.b64 {%0, %1}, %2;" : "=f"(lo), "=f"(hi) : "l"(v));
}
__device__ __forceinline__ uint64_t mul2(uint64_t a, uint64_t b) {
    uint64_t d;
    asm("mul.rn.f32x2 %0, %1, %2;" : "=l"(d) : "l"(a), "l"(b));
    return d;
}
__device__ __forceinline__ uint64_t fma2(uint64_t a, uint64_t b, uint64_t c) {
    uint64_t d;
    asm("fma.rn.f32x2 %0, %1, %2, %3;" : "=l"(d) : "l"(a), "l"(b), "l"(c));
    return d;
}
__device__ __forceinline__ uint64_t add2(uint64_t a, uint64_t b) {
    uint64_t d;
    asm("add.rn.f32x2 %0, %1, %2;" : "=l"(d) : "l"(a), "l"(b));
    return d;
}

// ---------------------------------------------------------------------------
// K0: pack known points into SoA; k2 = (x*x + y*y) + z*z per-op fp32
// ---------------------------------------------------------------------------
__global__ void prep_kernel(const float* __restrict__ known) {
    int j = blockIdx.x * 256 + threadIdx.x;
    if (j < B_ * M_) {
        float kx = known[3 * j + 0];
        float ky = known[3 * j + 1];
        float kz = known[3 * j + 2];
        g_kx[j] = kx; g_ky[j] = ky; g_kz[j] = kz;
        g_k2[j] = __fadd_rn(__fadd_rn(__fmul_rn(kx, kx), __fmul_rn(ky, ky)),
                            __fmul_rn(kz, kz));
    }
}

// ---------------------------------------------------------------------------
// K1: brute-force 1-NN, bitwise-matching reference arithmetic.
// Packed across k (f32x2): each lane is an ordinary fp32 RN op, so per-lane
//   dot = fmaf(uz,kz, fmaf(uy,ky, ux*kx));  d = fadd(fmaf(-2,dot,u2), k2)
// is bitwise identical to the scalar chain. Selection is the exact
// sequential strict-< scan (lo half first, then hi), ascending k.
// ---------------------------------------------------------------------------
#define NN_CHUNK 2048
__global__ void __launch_bounds__(256) nn_kernel(const float* __restrict__ unknown) {
    __shared__ __align__(16) float skx[NN_CHUNK];
    __shared__ __align__(16) float sky[NN_CHUNK];
    __shared__ __align__(16) float skz[NN_CHUNK];
    __shared__ __align__(16) float sk2[NN_CHUNK];
    const int b  = blockIdx.y;
    const int i0 = blockIdx.x * 1024;
    const int t  = threadIdx.x;

    uint64_t ux2[4], uy2[4], uz2[4], u22[4];
    float bd[4];
    int   bi[4];
#pragma unroll
    for (int u = 0; u < 4; u++) {
        int i = i0 + t + u * 256;
        const float* up = unknown + ((size_t)b * N_ + i) * 3;
        float ux = up[0], uy = up[1], uz = up[2];
        float u2 = __fadd_rn(__fadd_rn(__fmul_rn(ux, ux), __fmul_rn(uy, uy)),
                             __fmul_rn(uz, uz));
        ux2[u] = pk2(ux, ux); uy2[u] = pk2(uy, uy); uz2[u] = pk2(uz, uz);
        u22[u] = pk2(u2, u2);
        bd[u] = 3.4e38f; bi[u] = 0;
    }
    const uint64_t m22 = pk2(-2.0f, -2.0f);

    const size_t kb = (size_t)b * M_;
    for (int c0 = 0; c0 < M_; c0 += NN_CHUNK) {
        __syncthreads();
#pragma unroll
        for (int j = 0; j < 2; j++) {
            int pos = (t + j * 256) * 4;
            *(float4*)&skx[pos] = *(const float4*)&g_kx[kb + c0 + pos];
            *(float4*)&sky[pos] = *(const float4*)&g_ky[kb + c0 + pos];
            *(float4*)&skz[pos] = *(const float4*)&g_kz[kb + c0 + pos];
            *(float4*)&sk2[pos] = *(const float4*)&g_k2[kb + c0 + pos];
        }
        __syncthreads();

#pragma unroll 2
        for (int k = 0; k < NN_CHUNK; k += 2) {
            uint64_t kx2 = *(const uint64_t*)&skx[k];
            uint64_t ky2 = *(const uint64_t*)&sky[k];
            uint64_t kz2 = *(const uint64_t*)&skz[k];
            uint64_t k22 = *(const uint64_t*)&sk2[k];
#pragma unroll
            for (int u = 0; u < 4; u++) {
                uint64_t dot2 = mul2(ux2[u], kx2);
                dot2 = fma2(uy2[u], ky2, dot2);
                dot2 = fma2(uz2[u], kz2, dot2);
                uint64_t d2 = add2(fma2(m22, dot2, u22[u]), k22);
                float dlo, dhi;
                upk2(dlo, dhi, d2);
                if (dlo < bd[u]) { bd[u] = dlo; bi[u] = c0 + k; }
                if (dhi < bd[u]) { bd[u] = dhi; bi[u] = c0 + k + 1; }
            }
        }
    }
#pragma unroll
    for (int u = 0; u < 4; u++)
        g_idx[(size_t)b * N_ + i0 + t + u * 256] = bi[u];
}

// ---------------------------------------------------------------------------
// Tensor-core (tf32 mma.sync) fused GEMM.
//   Y = W @ X  (+ coalesced smem-staged gather of transposed P if GATHER)
//   BN at staging; deterministic stats partials; TRANSOUT writes Y[i][o].
// CTA tile 128(o) x 128(i), BK=32, 8 warps (4o x 2i), warp tile 32x64.
// ---------------------------------------------------------------------------
template <int KDIM, bool GATHER, bool BN, bool STATS, bool TRANSOUT, int MTOT>
__global__ void __launch_bounds__(256, 2) gemm_kernel(
    const float* __restrict__ W, int ldw, int woff,
    const float* __restrict__ X, int N,
    const float* __restrict__ P,
    const int*   __restrict__ idx,
    const float* __restrict__ bsc,
    const float* __restrict__ bbi,
    float* __restrict__ Y,
    float* __restrict__ part)
{
    __shared__ __align__(16) uint32_t SH[16384];   // 64KB: As|Bs, later G
    __shared__ int idbuf[128];

    const int b   = blockIdx.z;
    const int ob0 = blockIdx.y * 128;
    const int ib0 = blockIdx.x * 128;
    const int t   = threadIdx.x;
    const int lane = t & 31, wid = t >> 5;
    const int wo = wid >> 1, wn = wid & 1;
    const int gid = lane >> 2, tig = lane & 3;

    const float* Wp = W + woff;
    const float* Xb = X + (size_t)b * KDIM * N;

    float acc[2][8][4];
#pragma unroll
    for (int m = 0; m < 2; m++)
#pragma unroll
        for (int n = 0; n < 8; n++)
#pragma unroll
            for (int e = 0; e < 4; e++) acc[m][n][e] = 0.f;

    const int w_o   = t >> 1;
    const int w_kq0 = (t & 1) * 16;
    const int w_mt  = w_o >> 4, w_gid = w_o & 7, w_hi = (w_o >> 3) & 1;

    const int x_k   = t >> 3;
    const int x_i0  = (t & 7) * 16;
    const int x_s   = x_k >> 3;
    const int x_tig = x_k & 3, x_hi = (x_k >> 2) & 1;

    constexpr int NKT = KDIM / 32;
    int buf = 0;
    for (int kt = 0; kt < NKT; ++kt) {
        const int k0 = kt * 32;
        uint32_t* Ab = SH + buf * 4096;
        uint32_t* Bb = SH + 8192 + buf * 4096;

        {
            const float* wr = Wp + (size_t)(ob0 + w_o) * ldw + k0 + w_kq0;
#pragma unroll
            for (int j = 0; j < 4; j++) {
                float4 v = *(const float4*)(wr + j * 4);
                uint32_t q[4] = {cvt_tf32(v.x), cvt_tf32(v.y), cvt_tf32(v.z), cvt_tf32(v.w)};
#pragma unroll
                for (int e = 0; e < 4; e++) {
                    int kk = w_kq0 + j * 4 + e;
                    int s = kk >> 3, c = kk & 7;
                    Ab[(((s * 8 + w_mt) * 32 + w_gid * 4 + (c & 3)) << 2)
                       + w_hi + ((c >> 2) << 1)] = q[e];
                }
            }
        }
        {
            const float* xr = Xb + (size_t)(k0 + x_k) * N + ib0 + x_i0;
            float bs = 0.f, bb = 0.f;
            if (BN) { bs = bsc[k0 + x_k]; bb = bbi[k0 + x_k]; }
#pragma unroll
            for (int j = 0; j < 4; j++) {
                float4 v = *(const float4*)(xr + j * 4);
                if (BN) {
                    v.x = fmaxf(fmaf(v.x, bs, bb), 0.f);
                    v.y = fmaxf(fmaf(v.y, bs, bb), 0.f);
                    v.z = fmaxf(fmaf(v.z, bs, bb), 0.f);
                    v.w = fmaxf(fmaf(v.w, bs, bb), 0.f);
                }
                uint32_t q[4] = {cvt_tf32(v.x), cvt_tf32(v.y), cvt_tf32(v.z), cvt_tf32(v.w)};
#pragma unroll
                for (int e = 0; e < 4; e++) {
                    int i = x_i0 + j * 4 + e;
                    int nt = i >> 3, gg = i & 7;
                    Bb[(((x_s * 8 + (nt >> 1)) * 32 + gg * 4 + x_tig) << 2)
                       + (nt & 1) * 2 + x_hi] = q[e];
                }
            }
        }
        __syncthreads();
#pragma unroll
        for (int s = 0; s < 4; s++) {
            uint4 af[2];
            af[0] = *(const uint4*)&Ab[((s * 8 + wo * 2 + 0) * 32 + lane) << 2];
            af[1] = *(const uint4*)&Ab[((s * 8 + wo * 2 + 1) * 32 + lane) << 2];
            uint4 bf[4];
#pragma unroll
            for (int p = 0; p < 4; p++)
                bf[p] = *(const uint4*)&Bb[((s * 8 + wn * 4 + p) * 32 + lane) << 2];
#pragma unroll
            for (int m = 0; m < 2; m++)
#pragma unroll
                for (int p = 0; p < 4; p++) {
                    mma_tf32(acc[m][2 * p],     (const uint32_t*)&af[m], bf[p].x, bf[p].y);
                    mma_tf32(acc[m][2 * p + 1], (const uint32_t*)&af[m], bf[p].z, bf[p].w);
                }
        }
        buf ^= 1;
    }

    const int o_base = ob0 + wo * 32;
    const int i_base = ib0 + wn * 64;

    if (GATHER) {
        // coalesced smem-staged gather of transposed P: G[i][o] (128x128)
        __syncthreads();                         // mainloop smem reads done
        if (t < 128) idbuf[t] = idx[(size_t)b * N + ib0 + t];
        __syncthreads();
        float* G = (float*)SH;
#pragma unroll
        for (int j = 0; j < 16; j++) {
            int lin = t + j * 256;
            int r = lin >> 5, c4 = (lin & 31) << 2;
            const float* src = P + ((size_t)b * M_ + idbuf[r]) * MTOT + ob0 + c4;
            *(float4*)&G[r * 128 + c4] = *(const float4*)src;
        }
        __syncthreads();
        const int i0l = wn * 64 + tig * 2;
        const int o0l = wo * 32 + gid;
#pragma unroll
        for (int m = 0; m < 2; m++) {
            int oo = o0l + m * 16;
#pragma unroll
            for (int n = 0; n < 8; n++) {
                int ii = i0l + n * 8;
                acc[m][n][0] += G[ii * 128 + oo];
                acc[m][n][1] += G[(ii + 1) * 128 + oo];
                acc[m][n][2] += G[ii * 128 + oo + 8];
                acc[m][n][3] += G[(ii + 1) * 128 + oo + 8];
            }
        }
    }

    if (TRANSOUT) {
        // Y[b][i][o], row length MTOT; stores are 32B-sector efficient
#pragma unroll
        for (int m = 0; m < 2; m++)
#pragma unroll
            for (int n = 0; n < 8; n++) {
                int i_ = i_base + n * 8 + tig * 2;
                int o_ = o_base + m * 16 + gid;
                float* Yr = Y + ((size_t)b * N + i_) * MTOT;
                Yr[o_]            = acc[m][n][0];
                Yr[MTOT + o_]     = acc[m][n][1];
                Yr[o_ + 8]        = acc[m][n][2];
                Yr[MTOT + o_ + 8] = acc[m][n][3];
            }
    } else {
#pragma unroll
        for (int m = 0; m < 2; m++) {
            float* Y0 = Y + ((size_t)b * MTOT + o_base + m * 16 + gid) * N + i_base + tig * 2;
            float* Y8 = Y0 + (size_t)8 * N;
#pragma unroll
            for (int n = 0; n < 8; n++) {
                *(float2*)(Y0 + n * 8) = make_float2(acc[m][n][0], acc[m][n][1]);
                *(float2*)(Y8 + n * 8) = make_float2(acc[m][n][2], acc[m][n][3]);
            }
        }
    }

    if (STATS) {
        float s1[2][2], s2[2][2];
#pragma unroll
        for (int m = 0; m < 2; m++) {
            float a0 = 0.f, q0 = 0.f, a1 = 0.f, q1 = 0.f;
#pragma unroll
            for (int n = 0; n < 8; n++) {
                a0 += acc[m][n][0]; q0 = fmaf(acc[m][n][0], acc[m][n][0], q0);
                a0 += acc[m][n][1]; q0 = fmaf(acc[m][n][1], acc[m][n][1], q0);
                a1 += acc[m][n][2]; q1 = fmaf(acc[m][n][2], acc[m][n][2], q1);
                a1 += acc[m][n][3]; q1 = fmaf(acc[m][n][3], acc[m][n][3], q1);
            }
            s1[m][0] = a0; s2[m][0] = q0; s1[m][1] = a1; s2[m][1] = q1;
        }
#pragma unroll
        for (int m = 0; m < 2; m++)
#pragma unroll
            for (int h = 0; h < 2; h++) {
#pragma unroll
                for (int off = 1; off <= 2; off <<= 1) {
                    s1[m][h] += __shfl_xor_sync(0xffffffffu, s1[m][h], off);
                    s2[m][h] += __shfl_xor_sync(0xffffffffu, s2[m][h], off);
                }
            }
        float* sb1 = (float*)SH;
        float* sb2 = sb1 + 256;
        __syncthreads();
        if (tig == 0) {
#pragma unroll
            for (int m = 0; m < 2; m++)
#pragma unroll
                for (int h = 0; h < 2; h++) {
                    int ol = wo * 32 + m * 16 + h * 8 + gid;
                    sb1[wn * 128 + ol] = s1[m][h];
                    sb2[wn * 128 + ol] = s2[m][h];
                }
        }
        __syncthreads();
        if (t < 128) {
            float tot = sb1[t] + sb1[128 + t];
            part[(((size_t)b * MTOT + ob0 + t) * gridDim.x + blockIdx.x) * 2 + 0] = tot;
        } else {
            int o = t - 128;
            float tot = sb2[o] + sb2[128 + o];
            part[(((size_t)b * MTOT + ob0 + o) * gridDim.x + blockIdx.x) * 2 + 1] = tot;
        }
    }
}

// ---------------------------------------------------------------------------
// Finalize BN stats: one block per channel
// ---------------------------------------------------------------------------
template <int MTOT>
__global__ void __launch_bounds__(128) fin_kernel(
    const float* __restrict__ part,
    const float* __restrict__ gamma, const float* __restrict__ beta,
    float* __restrict__ sc, float* __restrict__ bi, float invN)
{
    const int o = blockIdx.x;
    const int t = threadIdx.x;
    float s1 = 0.f, s2 = 0.f;
    for (int b = 0; b < B_; b++) {
        const float* p = part + ((size_t)b * MTOT + o) * NT_ * 2;
        for (int q = t; q < NT_; q += 128) {
            s1 += p[q * 2 + 0];
            s2 += p[q * 2 + 1];
        }
    }
#pragma unroll
    for (int off = 16; off; off >>= 1) {
        s1 += __shfl_down_sync(0xffffffffu, s1, off);
        s2 += __shfl_down_sync(0xffffffffu, s2, off);
    }
    __shared__ float r1[4], r2[4];
    if ((t & 31) == 0) { r1[t >> 5] = s1; r2[t >> 5] = s2; }
    __syncthreads();
    if (t == 0) {
        s1 = r1[0] + r1[1] + r1[2] + r1[3];
        s2 = r2[0] + r2[1] + r2[2] + r2[3];
        float mean = s1 * invN;
        float var  = s2 * invN - mean * mean;
        float rstd = rsqrtf(var + EPS_);
        float s    = gamma[o] * rstd;
        sc[o] = s;
        bi[o] = beta[o] - mean * s;
    }
}

// ---------------------------------------------------------------------------
// Final elementwise BN+ReLU in-place on d_out
// ---------------------------------------------------------------------------
__global__ void __launch_bounds__(256) bnfin_kernel(
    float* __restrict__ Y, const float* __restrict__ sc, const float* __restrict__ bi)
{
    int row = blockIdx.y;
    int ch  = row & (H2_ - 1);
    size_t base = (size_t)row * N_;
    int i = (blockIdx.x * 256 + threadIdx.x) * 4;
    float4 v = *(float4*)(Y + base + i);
    float s = sc[ch], b = bi[ch];
    v.x = fmaxf(fmaf(v.x, s, b), 0.f);
    v.y = fmaxf(fmaf(v.y, s, b), 0.f);
    v.z = fmaxf(fmaf(v.z, s, b), 0.f);
    v.w = fmaxf(fmaf(v.w, s, b), 0.f);
    *(float4*)(Y + base + i) = v;
}

// ---------------------------------------------------------------------------
// Launch
// ---------------------------------------------------------------------------
extern "C" void kernel_launch(void* const* d_in, const int* in_sizes, int n_in,
                              void* d_out, int out_size)
{
    const float* unknown = (const float*)d_in[0];
    const float* known   = (const float*)d_in[1];
    const float* uf      = (const float*)d_in[2];
    const float* kf      = (const float*)d_in[3];
    const float* w1      = (const float*)d_in[4];
    const float* gamma1  = (const float*)d_in[5];
    const float* beta1   = (const float*)d_in[6];
    const float* w2      = (const float*)d_in[7];
    const float* gamma2  = (const float*)d_in[8];
    const float* beta2   = (const float*)d_in[9];
    float* out = (float*)d_out;

    float *pP, *ph, *pp1, *pp2, *ps1, *pb1, *ps2, *pb2;
    int* pidx;
    cudaGetSymbolAddress((void**)&pP,   g_P);
    cudaGetSymbolAddress((void**)&ph,   g_h);
    cudaGetSymbolAddress((void**)&pp1,  g_part1);
    cudaGetSymbolAddress((void**)&pp2,  g_part2);
    cudaGetSymbolAddress((void**)&ps1,  g_scale1);
    cudaGetSymbolAddress((void**)&pb1,  g_bias1);
    cudaGetSymbolAddress((void**)&ps2,  g_scale2);
    cudaGetSymbolAddress((void**)&pb2,  g_bias2);
    cudaGetSymbolAddress((void**)&pidx, g_idx);

    const float invN = 1.0f / (float)(B_ * N_);

    prep_kernel<<<(B_ * M_ + 255) / 256, 256>>>(known);

    nn_kernel<<<dim3(N_ / 1024, B_), 256>>>(unknown);

    // P_t[b][m][o] = (w1[:, :256] @ known_feats)^T   (transposed store)
    gemm_kernel<C2_, false, false, false, true, H1_>
        <<<dim3(M_ / 128, H1_ / 128, B_), 256>>>(
            w1, 384, 0, kf, M_, nullptr, nullptr, nullptr, nullptr, pP, nullptr);

    // h = w1[:, 256:] @ unknow_feats + gather(P_t, idx); stats1
    gemm_kernel<C1_, true, false, true, false, H1_>
        <<<dim3(N_ / 128, H1_ / 128, B_), 256>>>(
            w1, 384, C2_, uf, N_, pP, pidx, nullptr, nullptr, ph, pp1);

    fin_kernel<H1_><<<H1_, 128>>>(pp1, gamma1, beta1, ps1, pb1, invN);

    // out_pre = w2 @ relu(bn1(h)); stats2
    gemm_kernel<H1_, false, true, true, false, H2_>
        <<<dim3(N_ / 128, H2_ / 128, B_), 256>>>(
            w2, 256, 0, ph, N_, nullptr, nullptr, ps1, pb1, out, pp2);

    fin_kernel<H2_><<<H2_, 128>>>(pp2, gamma2, beta2, ps2, pb2, invN);

    bnfin_kernel<<<dim3(N_ / 1024, B_ * H2_), 256>>>(out, ps2, pb2);
}

// round 8
// speedup vs baseline: 2.1544x; 1.0080x over previous
#include <cuda_runtime.h>
#include <cstdint>

// ---------------------------------------------------------------------------
// Problem constants
// ---------------------------------------------------------------------------
#define B_   2
#define N_   65536
#define M_   16384
#define C1_  128
#define C2_  256
#define H1_  256
#define H2_  128
#define NT_  512
#define EPS_ 1e-5f

// ---------------------------------------------------------------------------
// Scratch (device globals -- no allocation allowed)
// ---------------------------------------------------------------------------
__device__ float  g_kx[B_ * M_], g_ky[B_ * M_], g_kz[B_ * M_], g_k2[B_ * M_];
__device__ int    g_idx[B_ * N_];
__device__ float  g_P[(size_t)B_ * M_ * H1_];      // TRANSPOSED: [b][m][o]
__device__ float  g_h[(size_t)B_ * H1_ * N_];
__device__ float  g_part1[(size_t)B_ * H1_ * NT_ * 2];
__device__ float  g_part2[(size_t)B_ * H2_ * NT_ * 2];
__device__ float  g_scale1[H1_], g_bias1[H1_];
__device__ float  g_scale2[H2_], g_bias2[H2_];

// ---------------------------------------------------------------------------
// helpers
// ---------------------------------------------------------------------------
__device__ __forceinline__ uint32_t cvt_tf32(float f) {
    uint32_t u;
    asm("cvt.rna.tf32.f32 %0, %1;" : "=r"(u) : "f"(f));
    return u;
}
__device__ __forceinline__ void mma_tf32(float* c, const uint32_t* a,
                                         uint32_t b0, uint32_t b1) {
    asm volatile(
        "mma.sync.aligned.m16n8k8.row.col.f32.tf32.tf32.f32 "
        "{%0,%1,%2,%3}, {%4,%5,%6,%7}, {%8,%9}, {%0,%1,%2,%3};\n"
        : "+f"(c[0]), "+f"(c[1]), "+f"(c[2]), "+f"(c[3])
        : "r"(a[0]), "r"(a[1]), "r"(a[2]), "r"(a[3]), "r"(b0), "r"(b1));
}
// packed f32x2 (each lane = independent fp32 RN op, bitwise == scalar chain)
__device__ __forceinline__ uint64_t pk2(float x, float y) {
    uint64_t r;
    asm("mov.b64 %0, {%1, %2};" : "=l"(r) : "f"(x), "f"(y));
    return r;
}
__device__ __forceinline__ void upk2(float& lo, float& hi, uint64_t v) {
    asm("mov.b64 {%0, %1}, %2;" : "=f"(lo), "=f"(hi) : "l"(v));
}
__device__ __forceinline__ uint64_t mul2(uint64_t a, uint64_t b) {
    uint64_t d;
    asm("mul.rn.f32x2 %0, %1, %2;" : "=l"(d) : "l"(a), "l"(b));
    return d;
}
__device__ __forceinline__ uint64_t fma2(uint64_t a, uint64_t b, uint64_t c) {
    uint64_t d;
    asm("fma.rn.f32x2 %0, %1, %2, %3;" : "=l"(d) : "l"(a), "l"(b), "l"(c));
    return d;
}
__device__ __forceinline__ uint64_t add2(uint64_t a, uint64_t b) {
    uint64_t d;
    asm("add.rn.f32x2 %0, %1, %2;" : "=l"(d) : "l"(a), "l"(b));
    return d;
}

// ---------------------------------------------------------------------------
// K0: pack known points into SoA; k2 = (x*x + y*y) + z*z per-op fp32
// ---------------------------------------------------------------------------
__global__ void prep_kernel(const float* __restrict__ known) {
    int j = blockIdx.x * 256 + threadIdx.x;
    if (j < B_ * M_) {
        float kx = known[3 * j + 0];
        float ky = known[3 * j + 1];
        float kz = known[3 * j + 2];
        g_kx[j] = kx; g_ky[j] = ky; g_kz[j] = kz;
        g_k2[j] = __fadd_rn(__fadd_rn(__fmul_rn(kx, kx), __fmul_rn(ky, ky)),
                            __fmul_rn(kz, kz));
    }
}

// ---------------------------------------------------------------------------
// K1: brute-force 1-NN, bitwise-matching reference arithmetic.
// Per-lane d chain (packed f32x2, each lane an fp32 RN op):
//   dot = fmaf(uz,kz, fmaf(uy,ky, ux*kx));  d = fadd(fmaf(-2,dot,u2), k2)
// GROUP-MIN selection: per 8 knowns compute gm = min of 8 bitwise-exact d's
// (7 FMNMX), update only when gm < bd (strict) -- rare branch; inside it,
// index = first k with d == gm, which equals the reference's sequential
// strict-< first-min scan result (see proof in round notes).
// ---------------------------------------------------------------------------
#define NN_CHUNK 2048
__global__ void __launch_bounds__(256) nn_kernel(const float* __restrict__ unknown) {
    __shared__ __align__(16) float skx[NN_CHUNK];
    __shared__ __align__(16) float sky[NN_CHUNK];
    __shared__ __align__(16) float skz[NN_CHUNK];
    __shared__ __align__(16) float sk2[NN_CHUNK];
    const int b  = blockIdx.y;
    const int i0 = blockIdx.x * 1024;
    const int t  = threadIdx.x;

    uint64_t ux2[4], uy2[4], uz2[4], u22[4];
    float bd[4];
    int   bi[4];
#pragma unroll
    for (int u = 0; u < 4; u++) {
        int i = i0 + t + u * 256;
        const float* up = unknown + ((size_t)b * N_ + i) * 3;
        float ux = up[0], uy = up[1], uz = up[2];
        float u2 = __fadd_rn(__fadd_rn(__fmul_rn(ux, ux), __fmul_rn(uy, uy)),
                             __fmul_rn(uz, uz));
        ux2[u] = pk2(ux, ux); uy2[u] = pk2(uy, uy); uz2[u] = pk2(uz, uz);
        u22[u] = pk2(u2, u2);
        bd[u] = 3.4e38f; bi[u] = 0;
    }
    const uint64_t m22 = pk2(-2.0f, -2.0f);

    const size_t kb = (size_t)b * M_;
    for (int c0 = 0; c0 < M_; c0 += NN_CHUNK) {
        __syncthreads();
#pragma unroll
        for (int j = 0; j < 2; j++) {
            int pos = (t + j * 256) * 4;
            *(float4*)&skx[pos] = *(const float4*)&g_kx[kb + c0 + pos];
            *(float4*)&sky[pos] = *(const float4*)&g_ky[kb + c0 + pos];
            *(float4*)&skz[pos] = *(const float4*)&g_kz[kb + c0 + pos];
            *(float4*)&sk2[pos] = *(const float4*)&g_k2[kb + c0 + pos];
        }
        __syncthreads();

        for (int k = 0; k < NN_CHUNK; k += 8) {
            // load 8 knowns (LDS.128 only), pack into f32x2 operands
            float4 xa = *(const float4*)&skx[k], xb = *(const float4*)&skx[k + 4];
            float4 ya = *(const float4*)&sky[k], yb = *(const float4*)&sky[k + 4];
            float4 za = *(const float4*)&skz[k], zb = *(const float4*)&skz[k + 4];
            float4 wa = *(const float4*)&sk2[k], wb = *(const float4*)&sk2[k + 4];
            uint64_t kx2[4] = {pk2(xa.x, xa.y), pk2(xa.z, xa.w), pk2(xb.x, xb.y), pk2(xb.z, xb.w)};
            uint64_t ky2[4] = {pk2(ya.x, ya.y), pk2(ya.z, ya.w), pk2(yb.x, yb.y), pk2(yb.z, yb.w)};
            uint64_t kz2[4] = {pk2(za.x, za.y), pk2(za.z, za.w), pk2(zb.x, zb.y), pk2(zb.z, zb.w)};
            uint64_t k22[4] = {pk2(wa.x, wa.y), pk2(wa.z, wa.w), pk2(wb.x, wb.y), pk2(wb.z, wb.w)};

#pragma unroll
            for (int u = 0; u < 4; u++) {
                float dl[4], dh[4];
#pragma unroll
                for (int p = 0; p < 4; p++) {
                    uint64_t dot2 = mul2(ux2[u], kx2[p]);
                    dot2 = fma2(uy2[u], ky2[p], dot2);
                    dot2 = fma2(uz2[u], kz2[p], dot2);
                    uint64_t d2 = add2(fma2(m22, dot2, u22[u]), k22[p]);
                    upk2(dl[p], dh[p], d2);
                }
                float m0 = fminf(fminf(dl[0], dh[0]), fminf(dl[1], dh[1]));
                float m1 = fminf(fminf(dl[2], dh[2]), fminf(dl[3], dh[3]));
                float gm = fminf(m0, m1);
                if (gm < bd[u]) {                 // rare
                    bd[u] = gm;
                    int base = c0 + k;
                    int id;
                    if      (dl[0] == gm) id = base + 0;
                    else if (dh[0] == gm) id = base + 1;
                    else if (dl[1] == gm) id = base + 2;
                    else if (dh[1] == gm) id = base + 3;
                    else if (dl[2] == gm) id = base + 4;
                    else if (dh[2] == gm) id = base + 5;
                    else if (dl[3] == gm) id = base + 6;
                    else                  id = base + 7;
                    bi[u] = id;
                }
            }
        }
    }
#pragma unroll
    for (int u = 0; u < 4; u++)
        g_idx[(size_t)b * N_ + i0 + t + u * 256] = bi[u];
}

// ---------------------------------------------------------------------------
// Tensor-core (tf32 mma.sync) fused GEMM.  (unchanged from round 7)
// ---------------------------------------------------------------------------
template <int KDIM, bool GATHER, bool BN, bool STATS, bool TRANSOUT, int MTOT>
__global__ void __launch_bounds__(256, 2) gemm_kernel(
    const float* __restrict__ W, int ldw, int woff,
    const float* __restrict__ X, int N,
    const float* __restrict__ P,
    const int*   __restrict__ idx,
    const float* __restrict__ bsc,
    const float* __restrict__ bbi,
    float* __restrict__ Y,
    float* __restrict__ part)
{
    __shared__ __align__(16) uint32_t SH[16384];   // 64KB: As|Bs, later G
    __shared__ int idbuf[128];

    const int b   = blockIdx.z;
    const int ob0 = blockIdx.y * 128;
    const int ib0 = blockIdx.x * 128;
    const int t   = threadIdx.x;
    const int lane = t & 31, wid = t >> 5;
    const int wo = wid >> 1, wn = wid & 1;
    const int gid = lane >> 2, tig = lane & 3;

    const float* Wp = W + woff;
    const float* Xb = X + (size_t)b * KDIM * N;

    float acc[2][8][4];
#pragma unroll
    for (int m = 0; m < 2; m++)
#pragma unroll
        for (int n = 0; n < 8; n++)
#pragma unroll
            for (int e = 0; e < 4; e++) acc[m][n][e] = 0.f;

    const int w_o   = t >> 1;
    const int w_kq0 = (t & 1) * 16;
    const int w_mt  = w_o >> 4, w_gid = w_o & 7, w_hi = (w_o >> 3) & 1;

    const int x_k   = t >> 3;
    const int x_i0  = (t & 7) * 16;
    const int x_s   = x_k >> 3;
    const int x_tig = x_k & 3, x_hi = (x_k >> 2) & 1;

    constexpr int NKT = KDIM / 32;
    int buf = 0;
    for (int kt = 0; kt < NKT; ++kt) {
        const int k0 = kt * 32;
        uint32_t* Ab = SH + buf * 4096;
        uint32_t* Bb = SH + 8192 + buf * 4096;

        {
            const float* wr = Wp + (size_t)(ob0 + w_o) * ldw + k0 + w_kq0;
#pragma unroll
            for (int j = 0; j < 4; j++) {
                float4 v = *(const float4*)(wr + j * 4);
                uint32_t q[4] = {cvt_tf32(v.x), cvt_tf32(v.y), cvt_tf32(v.z), cvt_tf32(v.w)};
#pragma unroll
                for (int e = 0; e < 4; e++) {
                    int kk = w_kq0 + j * 4 + e;
                    int s = kk >> 3, c = kk & 7;
                    Ab[(((s * 8 + w_mt) * 32 + w_gid * 4 + (c & 3)) << 2)
                       + w_hi + ((c >> 2) << 1)] = q[e];
                }
            }
        }
        {
            const float* xr = Xb + (size_t)(k0 + x_k) * N + ib0 + x_i0;
            float bs = 0.f, bb = 0.f;
            if (BN) { bs = bsc[k0 + x_k]; bb = bbi[k0 + x_k]; }
#pragma unroll
            for (int j = 0; j < 4; j++) {
                float4 v = *(const float4*)(xr + j * 4);
                if (BN) {
                    v.x = fmaxf(fmaf(v.x, bs, bb), 0.f);
                    v.y = fmaxf(fmaf(v.y, bs, bb), 0.f);
                    v.z = fmaxf(fmaf(v.z, bs, bb), 0.f);
                    v.w = fmaxf(fmaf(v.w, bs, bb), 0.f);
                }
                uint32_t q[4] = {cvt_tf32(v.x), cvt_tf32(v.y), cvt_tf32(v.z), cvt_tf32(v.w)};
#pragma unroll
                for (int e = 0; e < 4; e++) {
                    int i = x_i0 + j * 4 + e;
                    int nt = i >> 3, gg = i & 7;
                    Bb[(((x_s * 8 + (nt >> 1)) * 32 + gg * 4 + x_tig) << 2)
                       + (nt & 1) * 2 + x_hi] = q[e];
                }
            }
        }
        __syncthreads();
#pragma unroll
        for (int s = 0; s < 4; s++) {
            uint4 af[2];
            af[0] = *(const uint4*)&Ab[((s * 8 + wo * 2 + 0) * 32 + lane) << 2];
            af[1] = *(const uint4*)&Ab[((s * 8 + wo * 2 + 1) * 32 + lane) << 2];
            uint4 bf[4];
#pragma unroll
            for (int p = 0; p < 4; p++)
                bf[p] = *(const uint4*)&Bb[((s * 8 + wn * 4 + p) * 32 + lane) << 2];
#pragma unroll
            for (int m = 0; m < 2; m++)
#pragma unroll
                for (int p = 0; p < 4; p++) {
                    mma_tf32(acc[m][2 * p],     (const uint32_t*)&af[m], bf[p].x, bf[p].y);
                    mma_tf32(acc[m][2 * p + 1], (const uint32_t*)&af[m], bf[p].z, bf[p].w);
                }
        }
        buf ^= 1;
    }

    const int o_base = ob0 + wo * 32;
    const int i_base = ib0 + wn * 64;

    if (GATHER) {
        __syncthreads();
        if (t < 128) idbuf[t] = idx[(size_t)b * N + ib0 + t];
        __syncthreads();
        float* G = (float*)SH;
#pragma unroll
        for (int j = 0; j < 16; j++) {
            int lin = t + j * 256;
            int r = lin >> 5, c4 = (lin & 31) << 2;
            const float* src = P + ((size_t)b * M_ + idbuf[r]) * MTOT + ob0 + c4;
            *(float4*)&G[r * 128 + c4] = *(const float4*)src;
        }
        __syncthreads();
        const int i0l = wn * 64 + tig * 2;
        const int o0l = wo * 32 + gid;
#pragma unroll
        for (int m = 0; m < 2; m++) {
            int oo = o0l + m * 16;
#pragma unroll
            for (int n = 0; n < 8; n++) {
                int ii = i0l + n * 8;
                acc[m][n][0] += G[ii * 128 + oo];
                acc[m][n][1] += G[(ii + 1) * 128 + oo];
                acc[m][n][2] += G[ii * 128 + oo + 8];
                acc[m][n][3] += G[(ii + 1) * 128 + oo + 8];
            }
        }
    }

    if (TRANSOUT) {
#pragma unroll
        for (int m = 0; m < 2; m++)
#pragma unroll
            for (int n = 0; n < 8; n++) {
                int i_ = i_base + n * 8 + tig * 2;
                int o_ = o_base + m * 16 + gid;
                float* Yr = Y + ((size_t)b * N + i_) * MTOT;
                Yr[o_]            = acc[m][n][0];
                Yr[MTOT + o_]     = acc[m][n][1];
                Yr[o_ + 8]        = acc[m][n][2];
                Yr[MTOT + o_ + 8] = acc[m][n][3];
            }
    } else {
#pragma unroll
        for (int m = 0; m < 2; m++) {
            float* Y0 = Y + ((size_t)b * MTOT + o_base + m * 16 + gid) * N + i_base + tig * 2;
            float* Y8 = Y0 + (size_t)8 * N;
#pragma unroll
            for (int n = 0; n < 8; n++) {
                *(float2*)(Y0 + n * 8) = make_float2(acc[m][n][0], acc[m][n][1]);
                *(float2*)(Y8 + n * 8) = make_float2(acc[m][n][2], acc[m][n][3]);
            }
        }
    }

    if (STATS) {
        float s1[2][2], s2[2][2];
#pragma unroll
        for (int m = 0; m < 2; m++) {
            float a0 = 0.f, q0 = 0.f, a1 = 0.f, q1 = 0.f;
#pragma unroll
            for (int n = 0; n < 8; n++) {
                a0 += acc[m][n][0]; q0 = fmaf(acc[m][n][0], acc[m][n][0], q0);
                a0 += acc[m][n][1]; q0 = fmaf(acc[m][n][1], acc[m][n][1], q0);
                a1 += acc[m][n][2]; q1 = fmaf(acc[m][n][2], acc[m][n][2], q1);
                a1 += acc[m][n][3]; q1 = fmaf(acc[m][n][3], acc[m][n][3], q1);
            }
            s1[m][0] = a0; s2[m][0] = q0; s1[m][1] = a1; s2[m][1] = q1;
        }
#pragma unroll
        for (int m = 0; m < 2; m++)
#pragma unroll
            for (int h = 0; h < 2; h++) {
#pragma unroll
                for (int off = 1; off <= 2; off <<= 1) {
                    s1[m][h] += __shfl_xor_sync(0xffffffffu, s1[m][h], off);
                    s2[m][h] += __shfl_xor_sync(0xffffffffu, s2[m][h], off);
                }
            }
        float* sb1 = (float*)SH;
        float* sb2 = sb1 + 256;
        __syncthreads();
        if (tig == 0) {
#pragma unroll
            for (int m = 0; m < 2; m++)
#pragma unroll
                for (int h = 0; h < 2; h++) {
                    int ol = wo * 32 + m * 16 + h * 8 + gid;
                    sb1[wn * 128 + ol] = s1[m][h];
                    sb2[wn * 128 + ol] = s2[m][h];
                }
        }
        __syncthreads();
        if (t < 128) {
            float tot = sb1[t] + sb1[128 + t];
            part[(((size_t)b * MTOT + ob0 + t) * gridDim.x + blockIdx.x) * 2 + 0] = tot;
        } else {
            int o = t - 128;
            float tot = sb2[o] + sb2[128 + o];
            part[(((size_t)b * MTOT + ob0 + o) * gridDim.x + blockIdx.x) * 2 + 1] = tot;
        }
    }
}

// ---------------------------------------------------------------------------
// Finalize BN stats: one block per channel
// ---------------------------------------------------------------------------
template <int MTOT>
__global__ void __launch_bounds__(128) fin_kernel(
    const float* __restrict__ part,
    const float* __restrict__ gamma, const float* __restrict__ beta,
    float* __restrict__ sc, float* __restrict__ bi, float invN)
{
    const int o = blockIdx.x;
    const int t = threadIdx.x;
    float s1 = 0.f, s2 = 0.f;
    for (int b = 0; b < B_; b++) {
        const float* p = part + ((size_t)b * MTOT + o) * NT_ * 2;
        for (int q = t; q < NT_; q += 128) {
            s1 += p[q * 2 + 0];
            s2 += p[q * 2 + 1];
        }
    }
#pragma unroll
    for (int off = 16; off; off >>= 1) {
        s1 += __shfl_down_sync(0xffffffffu, s1, off);
        s2 += __shfl_down_sync(0xffffffffu, s2, off);
    }
    __shared__ float r1[4], r2[4];
    if ((t & 31) == 0) { r1[t >> 5] = s1; r2[t >> 5] = s2; }
    __syncthreads();
    if (t == 0) {
        s1 = r1[0] + r1[1] + r1[2] + r1[3];
        s2 = r2[0] + r2[1] + r2[2] + r2[3];
        float mean = s1 * invN;
        float var  = s2 * invN - mean * mean;
        float rstd = rsqrtf(var + EPS_);
        float s    = gamma[o] * rstd;
        sc[o] = s;
        bi[o] = beta[o] - mean * s;
    }
}

// ---------------------------------------------------------------------------
// Final elementwise BN+ReLU in-place on d_out
// ---------------------------------------------------------------------------
__global__ void __launch_bounds__(256) bnfin_kernel(
    float* __restrict__ Y, const float* __restrict__ sc, const float* __restrict__ bi)
{
    int row = blockIdx.y;
    int ch  = row & (H2_ - 1);
    size_t base = (size_t)row * N_;
    int i = (blockIdx.x * 256 + threadIdx.x) * 4;
    float4 v = *(float4*)(Y + base + i);
    float s = sc[ch], b = bi[ch];
    v.x = fmaxf(fmaf(v.x, s, b), 0.f);
    v.y = fmaxf(fmaf(v.y, s, b), 0.f);
    v.z = fmaxf(fmaf(v.z, s, b), 0.f);
    v.w = fmaxf(fmaf(v.w, s, b), 0.f);
    *(float4*)(Y + base + i) = v;
}

// ---------------------------------------------------------------------------
// Launch
// ---------------------------------------------------------------------------
extern "C" void kernel_launch(void* const* d_in, const int* in_sizes, int n_in,
                              void* d_out, int out_size)
{
    const float* unknown = (const float*)d_in[0];
    const float* known   = (const float*)d_in[1];
    const float* uf      = (const float*)d_in[2];
    const float* kf      = (const float*)d_in[3];
    const float* w1      = (const float*)d_in[4];
    const float* gamma1  = (const float*)d_in[5];
    const float* beta1   = (const float*)d_in[6];
    const float* w2      = (const float*)d_in[7];
    const float* gamma2  = (const float*)d_in[8];
    const float* beta2   = (const float*)d_in[9];
    float* out = (float*)d_out;

    float *pP, *ph, *pp1, *pp2, *ps1, *pb1, *ps2, *pb2;
    int* pidx;
    cudaGetSymbolAddress((void**)&pP,   g_P);
    cudaGetSymbolAddress((void**)&ph,   g_h);
    cudaGetSymbolAddress((void**)&pp1,  g_part1);
    cudaGetSymbolAddress((void**)&pp2,  g_part2);
    cudaGetSymbolAddress((void**)&ps1,  g_scale1);
    cudaGetSymbolAddress((void**)&pb1,  g_bias1);
    cudaGetSymbolAddress((void**)&ps2,  g_scale2);
    cudaGetSymbolAddress((void**)&pb2,  g_bias2);
    cudaGetSymbolAddress((void**)&pidx, g_idx);

    const float invN = 1.0f / (float)(B_ * N_);

    prep_kernel<<<(B_ * M_ + 255) / 256, 256>>>(known);

    nn_kernel<<<dim3(N_ / 1024, B_), 256>>>(unknown);

    // P_t[b][m][o] = (w1[:, :256] @ known_feats)^T   (transposed store)
    gemm_kernel<C2_, false, false, false, true, H1_>
        <<<dim3(M_ / 128, H1_ / 128, B_), 256>>>(
            w1, 384, 0, kf, M_, nullptr, nullptr, nullptr, nullptr, pP, nullptr);

    // h = w1[:, 256:] @ unknow_feats + gather(P_t, idx); stats1
    gemm_kernel<C1_, true, false, true, false, H1_>
        <<<dim3(N_ / 128, H1_ / 128, B_), 256>>>(
            w1, 384, C2_, uf, N_, pP, pidx, nullptr, nullptr, ph, pp1);

    fin_kernel<H1_><<<H1_, 128>>>(pp1, gamma1, beta1, ps1, pb1, invN);

    // out_pre = w2 @ relu(bn1(h)); stats2
    gemm_kernel<H1_, false, true, true, false, H2_>
        <<<dim3(N_ / 128, H2_ / 128, B_), 256>>>(
            w2, 256, 0, ph, N_, nullptr, nullptr, ps1, pb1, out, pp2);

    fin_kernel<H2_><<<H2_, 128>>>(pp2, gamma2, beta2, ps2, pb2, invN);

    bnfin_kernel<<<dim3(N_ / 1024, B_ * H2_), 256>>>(out, ps2, pb2);
}

// round 9
// speedup vs baseline: 2.4798x; 1.1510x over previous
#include <cuda_runtime.h>
#include <cstdint>

// ---------------------------------------------------------------------------
// Problem constants
// ---------------------------------------------------------------------------
#define B_   2
#define N_   65536
#define M_   16384
#define C1_  128
#define C2_  256
#define H1_  256
#define H2_  128
#define NT_  512
#define EPS_ 1e-5f
#define NN_CHUNK 2048

// ---------------------------------------------------------------------------
// Scratch (device globals -- no allocation allowed)
// ---------------------------------------------------------------------------
__device__ float  g_kx[B_ * M_], g_ky[B_ * M_], g_kz[B_ * M_], g_k2[B_ * M_];
__device__ int    g_idx[B_ * N_];
__device__ float  g_P[(size_t)B_ * M_ * H1_];      // TRANSPOSED: [b][m][o]
__device__ float  g_h[(size_t)B_ * H1_ * N_];
__device__ float  g_part1[(size_t)B_ * H1_ * NT_ * 2];
__device__ float  g_part2[(size_t)B_ * H2_ * NT_ * 2];
__device__ float  g_scale1[H1_], g_bias1[H1_];
__device__ float  g_scale2[H2_], g_bias2[H2_];

// ---------------------------------------------------------------------------
// helpers
// ---------------------------------------------------------------------------
__device__ __forceinline__ uint32_t cvt_tf32(float f) {
    uint32_t u;
    asm("cvt.rna.tf32.f32 %0, %1;" : "=r"(u) : "f"(f));
    return u;
}
__device__ __forceinline__ void mma_tf32(float* c, const uint32_t* a,
                                         uint32_t b0, uint32_t b1) {
    asm volatile(
        "mma.sync.aligned.m16n8k8.row.col.f32.tf32.tf32.f32 "
        "{%0,%1,%2,%3}, {%4,%5,%6,%7}, {%8,%9}, {%0,%1,%2,%3};\n"
        : "+f"(c[0]), "+f"(c[1]), "+f"(c[2]), "+f"(c[3])
        : "r"(a[0]), "r"(a[1]), "r"(a[2]), "r"(a[3]), "r"(b0), "r"(b1));
}
// packed f32x2 (each lane = independent fp32 RN op, bitwise == scalar chain)
__device__ __forceinline__ uint64_t pk2(float x, float y) {
    uint64_t r;
    asm("mov.b64 %0, {%1, %2};" : "=l"(r) : "f"(x), "f"(y));
    return r;
}
__device__ __forceinline__ void upk2(float& lo, float& hi, uint64_t v) {
    asm("mov.b64 {%0, %1}, %2;" : "=f"(lo), "=f"(hi) : "l"(v));
}
__device__ __forceinline__ uint64_t mul2(uint64_t a, uint64_t b) {
    uint64_t d;
    asm("mul.rn.f32x2 %0, %1, %2;" : "=l"(d) : "l"(a), "l"(b));
    return d;
}
__device__ __forceinline__ uint64_t fma2(uint64_t a, uint64_t b, uint64_t c) {
    uint64_t d;
    asm("fma.rn.f32x2 %0, %1, %2, %3;" : "=l"(d) : "l"(a), "l"(b), "l"(c));
    return d;
}
__device__ __forceinline__ uint64_t add2(uint64_t a, uint64_t b) {
    uint64_t d;
    asm("add.rn.f32x2 %0, %1, %2;" : "=l"(d) : "l"(a), "l"(b));
    return d;
}

// ---------------------------------------------------------------------------
// K0: pack known points into SoA; k2 = (x*x + y*y) + z*z per-op fp32
// ---------------------------------------------------------------------------
__global__ void prep_kernel(const float* __restrict__ known) {
    int j = blockIdx.x * 256 + threadIdx.x;
    if (j < B_ * M_) {
        float kx = known[3 * j + 0];
        float ky = known[3 * j + 1];
        float kz = known[3 * j + 2];
        g_kx[j] = kx; g_ky[j] = ky; g_kz[j] = kz;
        g_k2[j] = __fadd_rn(__fadd_rn(__fmul_rn(kx, kx), __fmul_rn(ky, ky)),
                            __fmul_rn(kz, kz));
    }
}

// ---------------------------------------------------------------------------
// NN body: brute-force 1-NN, bitwise-matching reference arithmetic.
// 256 threads, 2 unknowns/thread (512 per CTA). Packed f32x2 d-chain
// (bitwise == scalar), group-of-8 min + rare first-equal index recovery
// (== reference sequential strict-< scan; unchanged from round 8).
// smem operands loaded directly as ulonglong2 (no repacking MOVs).
// ---------------------------------------------------------------------------
__device__ __forceinline__ void nn_body(float* sm, int b, int i0,
                                        const float* __restrict__ unknown) {
    float* skx = sm;
    float* sky = sm + NN_CHUNK;
    float* skz = sm + 2 * NN_CHUNK;
    float* sk2 = sm + 3 * NN_CHUNK;
    const int t = threadIdx.x;

    uint64_t ux2[2], uy2[2], uz2[2], u22[2];
    float bd[2];
    int   bi[2];
#pragma unroll
    for (int u = 0; u < 2; u++) {
        int i = i0 + t + u * 256;
        const float* up = unknown + ((size_t)b * N_ + i) * 3;
        float ux = up[0], uy = up[1], uz = up[2];
        float u2 = __fadd_rn(__fadd_rn(__fmul_rn(ux, ux), __fmul_rn(uy, uy)),
                             __fmul_rn(uz, uz));
        ux2[u] = pk2(ux, ux); uy2[u] = pk2(uy, uy); uz2[u] = pk2(uz, uz);
        u22[u] = pk2(u2, u2);
        bd[u] = 3.4e38f; bi[u] = 0;
    }
    const uint64_t m22 = pk2(-2.0f, -2.0f);

    const size_t kb = (size_t)b * M_;
    for (int c0 = 0; c0 < M_; c0 += NN_CHUNK) {
        __syncthreads();
#pragma unroll
        for (int j = 0; j < 2; j++) {
            int pos = (t + j * 256) * 4;
            *(float4*)&skx[pos] = *(const float4*)&g_kx[kb + c0 + pos];
            *(float4*)&sky[pos] = *(const float4*)&g_ky[kb + c0 + pos];
            *(float4*)&skz[pos] = *(const float4*)&g_kz[kb + c0 + pos];
            *(float4*)&sk2[pos] = *(const float4*)&g_k2[kb + c0 + pos];
        }
        __syncthreads();

        for (int k = 0; k < NN_CHUNK; k += 8) {
            // LDS.128 loads ARE the packed f32x2 operands (adjacent k pairs)
            ulonglong2 x0 = *(const ulonglong2*)&skx[k];
            ulonglong2 x1 = *(const ulonglong2*)&skx[k + 4];
            ulonglong2 y0 = *(const ulonglong2*)&sky[k];
            ulonglong2 y1 = *(const ulonglong2*)&sky[k + 4];
            ulonglong2 z0 = *(const ulonglong2*)&skz[k];
            ulonglong2 z1 = *(const ulonglong2*)&skz[k + 4];
            ulonglong2 w0 = *(const ulonglong2*)&sk2[k];
            ulonglong2 w1v = *(const ulonglong2*)&sk2[k + 4];
            uint64_t kx2[4] = {x0.x, x0.y, x1.x, x1.y};
            uint64_t ky2[4] = {y0.x, y0.y, y1.x, y1.y};
            uint64_t kz2[4] = {z0.x, z0.y, z1.x, z1.y};
            uint64_t k22[4] = {w0.x, w0.y, w1v.x, w1v.y};

#pragma unroll
            for (int u = 0; u < 2; u++) {
                float dl[4], dh[4];
#pragma unroll
                for (int p = 0; p < 4; p++) {
                    uint64_t dot2 = mul2(ux2[u], kx2[p]);
                    dot2 = fma2(uy2[u], ky2[p], dot2);
                    dot2 = fma2(uz2[u], kz2[p], dot2);
                    uint64_t d2 = add2(fma2(m22, dot2, u22[u]), k22[p]);
                    upk2(dl[p], dh[p], d2);
                }
                float m0 = fminf(fminf(dl[0], dh[0]), fminf(dl[1], dh[1]));
                float m1 = fminf(fminf(dl[2], dh[2]), fminf(dl[3], dh[3]));
                float gm = fminf(m0, m1);
                if (gm < bd[u]) {                 // rare
                    bd[u] = gm;
                    int base = c0 + k;
                    int id;
                    if      (dl[0] == gm) id = base + 0;
                    else if (dh[0] == gm) id = base + 1;
                    else if (dl[1] == gm) id = base + 2;
                    else if (dh[1] == gm) id = base + 3;
                    else if (dl[2] == gm) id = base + 4;
                    else if (dh[2] == gm) id = base + 5;
                    else if (dl[3] == gm) id = base + 6;
                    else                  id = base + 7;
                    bi[u] = id;
                }
            }
        }
    }
#pragma unroll
    for (int u = 0; u < 2; u++)
        g_idx[(size_t)b * N_ + i0 + t + u * 256] = bi[u];
}

// ---------------------------------------------------------------------------
// Tensor-core (tf32 mma.sync) fused GEMM body (shared by standalone + fused).
// ---------------------------------------------------------------------------
template <int KDIM, bool GATHER, bool BN, bool STATS, bool TRANSOUT, int MTOT>
__device__ __forceinline__ void gemm_body(
    uint32_t* SH, int* idbuf,
    int b, int ob0, int ib0, int nbx, int bx,
    const float* __restrict__ W, int ldw, int woff,
    const float* __restrict__ X, int N,
    const float* __restrict__ P,
    const int*   __restrict__ idx,
    const float* __restrict__ bsc,
    const float* __restrict__ bbi,
    float* __restrict__ Y,
    float* __restrict__ part)
{
    const int t   = threadIdx.x;
    const int lane = t & 31, wid = t >> 5;
    const int wo = wid >> 1, wn = wid & 1;
    const int gid = lane >> 2, tig = lane & 3;

    const float* Wp = W + woff;
    const float* Xb = X + (size_t)b * KDIM * N;

    float acc[2][8][4];
#pragma unroll
    for (int m = 0; m < 2; m++)
#pragma unroll
        for (int n = 0; n < 8; n++)
#pragma unroll
            for (int e = 0; e < 4; e++) acc[m][n][e] = 0.f;

    const int w_o   = t >> 1;
    const int w_kq0 = (t & 1) * 16;
    const int w_mt  = w_o >> 4, w_gid = w_o & 7, w_hi = (w_o >> 3) & 1;

    const int x_k   = t >> 3;
    const int x_i0  = (t & 7) * 16;
    const int x_s   = x_k >> 3;
    const int x_tig = x_k & 3, x_hi = (x_k >> 2) & 1;

    constexpr int NKT = KDIM / 32;
    int buf = 0;
    for (int kt = 0; kt < NKT; ++kt) {
        const int k0 = kt * 32;
        uint32_t* Ab = SH + buf * 4096;
        uint32_t* Bb = SH + 8192 + buf * 4096;

        {
            const float* wr = Wp + (size_t)(ob0 + w_o) * ldw + k0 + w_kq0;
#pragma unroll
            for (int j = 0; j < 4; j++) {
                float4 v = *(const float4*)(wr + j * 4);
                uint32_t q[4] = {cvt_tf32(v.x), cvt_tf32(v.y), cvt_tf32(v.z), cvt_tf32(v.w)};
#pragma unroll
                for (int e = 0; e < 4; e++) {
                    int kk = w_kq0 + j * 4 + e;
                    int s = kk >> 3, c = kk & 7;
                    Ab[(((s * 8 + w_mt) * 32 + w_gid * 4 + (c & 3)) << 2)
                       + w_hi + ((c >> 2) << 1)] = q[e];
                }
            }
        }
        {
            const float* xr = Xb + (size_t)(k0 + x_k) * N + ib0 + x_i0;
            float bs = 0.f, bb = 0.f;
            if (BN) { bs = bsc[k0 + x_k]; bb = bbi[k0 + x_k]; }
#pragma unroll
            for (int j = 0; j < 4; j++) {
                float4 v = *(const float4*)(xr + j * 4);
                if (BN) {
                    v.x = fmaxf(fmaf(v.x, bs, bb), 0.f);
                    v.y = fmaxf(fmaf(v.y, bs, bb), 0.f);
                    v.z = fmaxf(fmaf(v.z, bs, bb), 0.f);
                    v.w = fmaxf(fmaf(v.w, bs, bb), 0.f);
                }
                uint32_t q[4] = {cvt_tf32(v.x), cvt_tf32(v.y), cvt_tf32(v.z), cvt_tf32(v.w)};
#pragma unroll
                for (int e = 0; e < 4; e++) {
                    int i = x_i0 + j * 4 + e;
                    int nt = i >> 3, gg = i & 7;
                    Bb[(((x_s * 8 + (nt >> 1)) * 32 + gg * 4 + x_tig) << 2)
                       + (nt & 1) * 2 + x_hi] = q[e];
                }
            }
        }
        __syncthreads();
#pragma unroll
        for (int s = 0; s < 4; s++) {
            uint4 af[2];
            af[0] = *(const uint4*)&Ab[((s * 8 + wo * 2 + 0) * 32 + lane) << 2];
            af[1] = *(const uint4*)&Ab[((s * 8 + wo * 2 + 1) * 32 + lane) << 2];
            uint4 bf[4];
#pragma unroll
            for (int p = 0; p < 4; p++)
                bf[p] = *(const uint4*)&Bb[((s * 8 + wn * 4 + p) * 32 + lane) << 2];
#pragma unroll
            for (int m = 0; m < 2; m++)
#pragma unroll
                for (int p = 0; p < 4; p++) {
                    mma_tf32(acc[m][2 * p],     (const uint32_t*)&af[m], bf[p].x, bf[p].y);
                    mma_tf32(acc[m][2 * p + 1], (const uint32_t*)&af[m], bf[p].z, bf[p].w);
                }
        }
        buf ^= 1;
    }

    const int o_base = ob0 + wo * 32;
    const int i_base = ib0 + wn * 64;

    if (GATHER) {
        __syncthreads();
        if (t < 128) idbuf[t] = idx[(size_t)b * N + ib0 + t];
        __syncthreads();
        float* G = (float*)SH;
#pragma unroll
        for (int j = 0; j < 16; j++) {
            int lin = t + j * 256;
            int r = lin >> 5, c4 = (lin & 31) << 2;
            const float* src = P + ((size_t)b * M_ + idbuf[r]) * MTOT + ob0 + c4;
            *(float4*)&G[r * 128 + c4] = *(const float4*)src;
        }
        __syncthreads();
        const int i0l = wn * 64 + tig * 2;
        const int o0l = wo * 32 + gid;
#pragma unroll
        for (int m = 0; m < 2; m++) {
            int oo = o0l + m * 16;
#pragma unroll
            for (int n = 0; n < 8; n++) {
                int ii = i0l + n * 8;
                acc[m][n][0] += G[ii * 128 + oo];
                acc[m][n][1] += G[(ii + 1) * 128 + oo];
                acc[m][n][2] += G[ii * 128 + oo + 8];
                acc[m][n][3] += G[(ii + 1) * 128 + oo + 8];
            }
        }
    }

    if (TRANSOUT) {
#pragma unroll
        for (int m = 0; m < 2; m++)
#pragma unroll
            for (int n = 0; n < 8; n++) {
                int i_ = i_base + n * 8 + tig * 2;
                int o_ = o_base + m * 16 + gid;
                float* Yr = Y + ((size_t)b * N + i_) * MTOT;
                Yr[o_]            = acc[m][n][0];
                Yr[MTOT + o_]     = acc[m][n][1];
                Yr[o_ + 8]        = acc[m][n][2];
                Yr[MTOT + o_ + 8] = acc[m][n][3];
            }
    } else {
#pragma unroll
        for (int m = 0; m < 2; m++) {
            float* Y0 = Y + ((size_t)b * MTOT + o_base + m * 16 + gid) * N + i_base + tig * 2;
            float* Y8 = Y0 + (size_t)8 * N;
#pragma unroll
            for (int n = 0; n < 8; n++) {
                *(float2*)(Y0 + n * 8) = make_float2(acc[m][n][0], acc[m][n][1]);
                *(float2*)(Y8 + n * 8) = make_float2(acc[m][n][2], acc[m][n][3]);
            }
        }
    }

    if (STATS) {
        float s1[2][2], s2[2][2];
#pragma unroll
        for (int m = 0; m < 2; m++) {
            float a0 = 0.f, q0 = 0.f, a1 = 0.f, q1 = 0.f;
#pragma unroll
            for (int n = 0; n < 8; n++) {
                a0 += acc[m][n][0]; q0 = fmaf(acc[m][n][0], acc[m][n][0], q0);
                a0 += acc[m][n][1]; q0 = fmaf(acc[m][n][1], acc[m][n][1], q0);
                a1 += acc[m][n][2]; q1 = fmaf(acc[m][n][2], acc[m][n][2], q1);
                a1 += acc[m][n][3]; q1 = fmaf(acc[m][n][3], acc[m][n][3], q1);
            }
            s1[m][0] = a0; s2[m][0] = q0; s1[m][1] = a1; s2[m][1] = q1;
        }
#pragma unroll
        for (int m = 0; m < 2; m++)
#pragma unroll
            for (int h = 0; h < 2; h++) {
#pragma unroll
                for (int off = 1; off <= 2; off <<= 1) {
                    s1[m][h] += __shfl_xor_sync(0xffffffffu, s1[m][h], off);
                    s2[m][h] += __shfl_xor_sync(0xffffffffu, s2[m][h], off);
                }
            }
        float* sb1 = (float*)SH;
        float* sb2 = sb1 + 256;
        __syncthreads();
        if (tig == 0) {
#pragma unroll
            for (int m = 0; m < 2; m++)
#pragma unroll
                for (int h = 0; h < 2; h++) {
                    int ol = wo * 32 + m * 16 + h * 8 + gid;
                    sb1[wn * 128 + ol] = s1[m][h];
                    sb2[wn * 128 + ol] = s2[m][h];
                }
        }
        __syncthreads();
        if (t < 128) {
            float tot = sb1[t] + sb1[128 + t];
            part[(((size_t)b * MTOT + ob0 + t) * nbx + bx) * 2 + 0] = tot;
        } else {
            int o = t - 128;
            float tot = sb2[o] + sb2[128 + o];
            part[(((size_t)b * MTOT + ob0 + o) * nbx + bx) * 2 + 1] = tot;
        }
    }
}

// ---------------------------------------------------------------------------
// Standalone GEMM kernel (K3, K5)
// ---------------------------------------------------------------------------
template <int KDIM, bool GATHER, bool BN, bool STATS, bool TRANSOUT, int MTOT>
__global__ void __launch_bounds__(256, 2) gemm_kernel(
    const float* __restrict__ W, int ldw, int woff,
    const float* __restrict__ X, int N,
    const float* __restrict__ P,
    const int*   __restrict__ idx,
    const float* __restrict__ bsc,
    const float* __restrict__ bbi,
    float* __restrict__ Y,
    float* __restrict__ part)
{
    __shared__ __align__(16) uint32_t SH[16384];
    __shared__ int idbuf[128];
    gemm_body<KDIM, GATHER, BN, STATS, TRANSOUT, MTOT>(
        SH, idbuf, blockIdx.z, blockIdx.y * 128, blockIdx.x * 128,
        gridDim.x, blockIdx.x,
        W, ldw, woff, X, N, P, idx, bsc, bbi, Y, part);
}

// ---------------------------------------------------------------------------
// FUSED kernel: bids [0,256) run 1-NN (512 unknowns each);
//               bids [256,768) run K2 (P_t = (w1a @ kf)^T).
// NN CTAs dispatch first and pin all SMs; K2 CTAs co-reside (2 CTAs/SM)
// and execute on the tensor pipe underneath the fma-bound NN.
// ---------------------------------------------------------------------------
__global__ void __launch_bounds__(256, 2) fused_nn_k2_kernel(
    const float* __restrict__ unknown,
    const float* __restrict__ w1,
    const float* __restrict__ kf,
    float* __restrict__ P)
{
    __shared__ __align__(16) uint32_t SH[16384];
    __shared__ int idbuf[128];
    const int bid = blockIdx.x;
    if (bid < 256) {
        nn_body((float*)SH, bid >> 7, (bid & 127) * 512, unknown);
    } else {
        const int g  = bid - 256;        // 0..511
        const int bx = g & 127;          // i-tile (m direction)
        const int oy = (g >> 7) & 1;     // o-tile
        const int b  = g >> 8;           // batch
        gemm_body<C2_, false, false, false, true, H1_>(
            SH, idbuf, b, oy * 128, bx * 128, 128, bx,
            w1, 384, 0, kf, M_, nullptr, nullptr, nullptr, nullptr,
            P, nullptr);
    }
}

// ---------------------------------------------------------------------------
// Finalize BN stats: one block per channel
// ---------------------------------------------------------------------------
template <int MTOT>
__global__ void __launch_bounds__(128) fin_kernel(
    const float* __restrict__ part,
    const float* __restrict__ gamma, const float* __restrict__ beta,
    float* __restrict__ sc, float* __restrict__ bi, float invN)
{
    const int o = blockIdx.x;
    const int t = threadIdx.x;
    float s1 = 0.f, s2 = 0.f;
    for (int b = 0; b < B_; b++) {
        const float* p = part + ((size_t)b * MTOT + o) * NT_ * 2;
        for (int q = t; q < NT_; q += 128) {
            s1 += p[q * 2 + 0];
            s2 += p[q * 2 + 1];
        }
    }
#pragma unroll
    for (int off = 16; off; off >>= 1) {
        s1 += __shfl_down_sync(0xffffffffu, s1, off);
        s2 += __shfl_down_sync(0xffffffffu, s2, off);
    }
    __shared__ float r1[4], r2[4];
    if ((t & 31) == 0) { r1[t >> 5] = s1; r2[t >> 5] = s2; }
    __syncthreads();
    if (t == 0) {
        s1 = r1[0] + r1[1] + r1[2] + r1[3];
        s2 = r2[0] + r2[1] + r2[2] + r2[3];
        float mean = s1 * invN;
        float var  = s2 * invN - mean * mean;
        float rstd = rsqrtf(var + EPS_);
        float s    = gamma[o] * rstd;
        sc[o] = s;
        bi[o] = beta[o] - mean * s;
    }
}

// ---------------------------------------------------------------------------
// Final elementwise BN+ReLU in-place on d_out
// ---------------------------------------------------------------------------
__global__ void __launch_bounds__(256) bnfin_kernel(
    float* __restrict__ Y, const float* __restrict__ sc, const float* __restrict__ bi)
{
    int row = blockIdx.y;
    int ch  = row & (H2_ - 1);
    size_t base = (size_t)row * N_;
    int i = (blockIdx.x * 256 + threadIdx.x) * 4;
    float4 v = *(float4*)(Y + base + i);
    float s = sc[ch], b = bi[ch];
    v.x = fmaxf(fmaf(v.x, s, b), 0.f);
    v.y = fmaxf(fmaf(v.y, s, b), 0.f);
    v.z = fmaxf(fmaf(v.z, s, b), 0.f);
    v.w = fmaxf(fmaf(v.w, s, b), 0.f);
    *(float4*)(Y + base + i) = v;
}

// ---------------------------------------------------------------------------
// Launch
// ---------------------------------------------------------------------------
extern "C" void kernel_launch(void* const* d_in, const int* in_sizes, int n_in,
                              void* d_out, int out_size)
{
    const float* unknown = (const float*)d_in[0];
    const float* known   = (const float*)d_in[1];
    const float* uf      = (const float*)d_in[2];
    const float* kf      = (const float*)d_in[3];
    const float* w1      = (const float*)d_in[4];
    const float* gamma1  = (const float*)d_in[5];
    const float* beta1   = (const float*)d_in[6];
    const float* w2      = (const float*)d_in[7];
    const float* gamma2  = (const float*)d_in[8];
    const float* beta2   = (const float*)d_in[9];
    float* out = (float*)d_out;

    float *pP, *ph, *pp1, *pp2, *ps1, *pb1, *ps2, *pb2;
    int* pidx;
    cudaGetSymbolAddress((void**)&pP,   g_P);
    cudaGetSymbolAddress((void**)&ph,   g_h);
    cudaGetSymbolAddress((void**)&pp1,  g_part1);
    cudaGetSymbolAddress((void**)&pp2,  g_part2);
    cudaGetSymbolAddress((void**)&ps1,  g_scale1);
    cudaGetSymbolAddress((void**)&pb1,  g_bias1);
    cudaGetSymbolAddress((void**)&ps2,  g_scale2);
    cudaGetSymbolAddress((void**)&pb2,  g_bias2);
    cudaGetSymbolAddress((void**)&pidx, g_idx);

    const float invN = 1.0f / (float)(B_ * N_);

    prep_kernel<<<(B_ * M_ + 255) / 256, 256>>>(known);

    // NN (bids 0..255) + K2 P_t-GEMM (bids 256..767) in one launch
    fused_nn_k2_kernel<<<768, 256>>>(unknown, w1, kf, pP);

    // h = w1[:, 256:] @ unknow_feats + gather(P_t, idx); stats1
    gemm_kernel<C1_, true, false, true, false, H1_>
        <<<dim3(N_ / 128, H1_ / 128, B_), 256>>>(
            w1, 384, C2_, uf, N_, pP, pidx, nullptr, nullptr, ph, pp1);

    fin_kernel<H1_><<<H1_, 128>>>(pp1, gamma1, beta1, ps1, pb1, invN);

    // out_pre = w2 @ relu(bn1(h)); stats2
    gemm_kernel<H1_, false, true, true, false, H2_>
        <<<dim3(N_ / 128, H2_ / 128, B_), 256>>>(
            w2, 256, 0, ph, N_, nullptr, nullptr, ps1, pb1, out, pp2);

    fin_kernel<H2_><<<H2_, 128>>>(pp2, gamma2, beta2, ps2, pb2, invN);

    bnfin_kernel<<<dim3(N_ / 1024, B_ * H2_), 256>>>(out, ps2, pb2);
}

// round 10
// speedup vs baseline: 2.6011x; 1.0489x over previous
#include <cuda_runtime.h>
#include <cstdint>

// ---------------------------------------------------------------------------
// Problem constants
// ---------------------------------------------------------------------------
#define B_   2
#define N_   65536
#define M_   16384
#define C1_  128
#define C2_  256
#define H1_  256
#define H2_  128
#define NT_  512
#define EPS_ 1e-5f
#define CELLS 32768          // 32^3 grid per batch

// ---------------------------------------------------------------------------
// Scratch (device globals -- no allocation allowed)
// ---------------------------------------------------------------------------
__device__ int    g_idx[B_ * N_];
__device__ float  g_P[(size_t)B_ * M_ * H1_];      // TRANSPOSED: [b][m][o]
__device__ float  g_h[(size_t)B_ * H1_ * N_];
__device__ float  g_part1[(size_t)B_ * H1_ * NT_ * 2];
__device__ float  g_part2[(size_t)B_ * H2_ * NT_ * 2];
__device__ float  g_scale1[H1_], g_bias1[H1_];
__device__ float  g_scale2[H2_], g_bias2[H2_];

// grid-NN scratch
__device__ int    g_kcnt[B_ * CELLS], g_kstart[B_ * CELLS], g_kcur[B_ * CELLS];
__device__ int    g_qcnt[B_ * CELLS], g_qstart[B_ * CELLS], g_qcur[B_ * CELLS];
__device__ int    g_kcell[B_ * M_],  g_qcell[B_ * N_];
__device__ __align__(16) float4 g_ksort[B_ * M_];
__device__ __align__(16) float4 g_qsort[B_ * N_];
__device__ int    g_korig[B_ * M_], g_qorig[B_ * N_];

// ---------------------------------------------------------------------------
// helpers
// ---------------------------------------------------------------------------
__device__ __forceinline__ uint32_t cvt_tf32(float f) {
    uint32_t u;
    asm("cvt.rna.tf32.f32 %0, %1;" : "=r"(u) : "f"(f));
    return u;
}
__device__ __forceinline__ void mma_tf32(float* c, const uint32_t* a,
                                         uint32_t b0, uint32_t b1) {
    asm volatile(
        "mma.sync.aligned.m16n8k8.row.col.f32.tf32.tf32.f32 "
        "{%0,%1,%2,%3}, {%4,%5,%6,%7}, {%8,%9}, {%0,%1,%2,%3};\n"
        : "+f"(c[0]), "+f"(c[1]), "+f"(c[2]), "+f"(c[3])
        : "r"(a[0]), "r"(a[1]), "r"(a[2]), "r"(a[3]), "r"(b0), "r"(b1));
}
__device__ __forceinline__ int cellof(float v) {
    int c = __float2int_rd((v + 4.0f) * 4.0f);
    return min(31, max(0, c));
}

// ---------------------------------------------------------------------------
// Binning: zero counters -> histogram -> scan -> scatter
// ---------------------------------------------------------------------------
__global__ void zero_kernel() {
    int i = blockIdx.x * 256 + threadIdx.x;
    if (i < B_ * CELLS) { g_kcnt[i] = 0; g_qcnt[i] = 0; }
}

__global__ void hist_kernel(const float* __restrict__ unknown,
                            const float* __restrict__ known) {
    int j = blockIdx.x * 256 + threadIdx.x;
    if (j < B_ * M_) {
        float x = known[3 * j], y = known[3 * j + 1], z = known[3 * j + 2];
        int cell = (cellof(z) * 32 + cellof(y)) * 32 + cellof(x);
        g_kcell[j] = cell;
        atomicAdd(&g_kcnt[(j / M_) * CELLS + cell], 1);
    } else {
        int q = j - B_ * M_;
        if (q < B_ * N_) {
            float x = unknown[3 * q], y = unknown[3 * q + 1], z = unknown[3 * q + 2];
            int cell = (cellof(z) * 32 + cellof(y)) * 32 + cellof(x);
            g_qcell[q] = cell;
            atomicAdd(&g_qcnt[(q / N_) * CELLS + cell], 1);
        }
    }
}

// one block per (array, batch): 0,1 = knowns b0/b1; 2,3 = queries b0/b1
__global__ void __launch_bounds__(1024) scan_kernel() {
    const int w = blockIdx.x;
    int* cnt;  int* start;  int* cur;
    if (w < 2) { cnt = g_kcnt + w * CELLS; start = g_kstart + w * CELLS; cur = g_kcur + w * CELLS; }
    else { int b = w - 2; cnt = g_qcnt + b * CELLS; start = g_qstart + b * CELLS; cur = g_qcur + b * CELLS; }
    const int t = threadIdx.x;
    int loc[32]; int s = 0;
#pragma unroll
    for (int i = 0; i < 32; i++) { loc[i] = s; s += cnt[t * 32 + i]; }
    const int lane = t & 31, wid = t >> 5;
    int v = s;
#pragma unroll
    for (int off = 1; off < 32; off <<= 1) {
        int n = __shfl_up_sync(0xffffffffu, v, off);
        if (lane >= off) v += n;
    }
    __shared__ int ws[32];
    if (lane == 31) ws[wid] = v;
    __syncthreads();
    if (wid == 0) {
        int x = ws[lane];
#pragma unroll
        for (int off = 1; off < 32; off <<= 1) {
            int n = __shfl_up_sync(0xffffffffu, x, off);
            if (lane >= off) x += n;
        }
        ws[lane] = x;
    }
    __syncthreads();
    int base = v - s + (wid > 0 ? ws[wid - 1] : 0);
#pragma unroll
    for (int i = 0; i < 32; i++) {
        int val = base + loc[i];
        start[t * 32 + i] = val;
        cur[t * 32 + i] = val;
    }
}

__global__ void scatter_kernel(const float* __restrict__ unknown,
                               const float* __restrict__ known) {
    int j = blockIdx.x * 256 + threadIdx.x;
    if (j < B_ * M_) {
        int b = j / M_;
        float x = known[3 * j], y = known[3 * j + 1], z = known[3 * j + 2];
        float k2 = __fadd_rn(__fadd_rn(__fmul_rn(x, x), __fmul_rn(y, y)),
                             __fmul_rn(z, z));
        int pos = atomicAdd(&g_kcur[b * CELLS + g_kcell[j]], 1);
        g_ksort[b * M_ + pos] = make_float4(x, y, z, k2);
        g_korig[b * M_ + pos] = j - b * M_;
    } else {
        int q = j - B_ * M_;
        if (q < B_ * N_) {
            int b = q / N_;
            float x = unknown[3 * q], y = unknown[3 * q + 1], z = unknown[3 * q + 2];
            float u2 = __fadd_rn(__fadd_rn(__fmul_rn(x, x), __fmul_rn(y, y)),
                                 __fmul_rn(z, z));
            int pos = atomicAdd(&g_qcur[b * CELLS + g_qcell[q]], 1);
            g_qsort[(size_t)b * N_ + pos] = make_float4(x, y, z, u2);
            g_qorig[(size_t)b * N_ + pos] = q - b * N_;
        }
    }
}

// ---------------------------------------------------------------------------
// Grid-pruned exact 1-NN.
// d per candidate uses the EXACT reference chain:
//   dot = fmaf(uz,kz, fmaf(uy,ky, ux*kx));  d = fadd(fmaf(-2,dot,u2), k2)
// Selection: (min d, then min ORIGINAL index among bitwise-equal d) ==
// reference's sequential first strict-< min (order-independent).
// Ring stop: unexamined points (Chebyshev >= r) have true dist^2 >=
// ((r-1)*0.25)^2; 4e-3 margin covers fp32 error of the d chain.
// ---------------------------------------------------------------------------
__device__ __forceinline__ void nn_search_body(int gq) {
    const int b = gq / N_;
    const float4 q = g_qsort[gq];
    const int oq = g_qorig[gq];
    const int qx = cellof(q.x), qy = cellof(q.y), qz = cellof(q.z);
    float bd = 3.4e38f; int bi = 0;
    const float4* kp = g_ksort + (size_t)b * M_;
    const int*    ko = g_korig + (size_t)b * M_;
    const int*    st = g_kstart + b * CELLS;
    const int*    ct = g_kcnt + b * CELLS;

    for (int r = 0; r <= 31; r++) {
        if (r > 0) {
            float rr = (float)(r - 1) * 0.25f;
            if (bd + 4e-3f <= rr * rr) break;
        }
        int zlo = max(qz - r, 0), zhi = min(qz + r, 31);
        for (int cz = zlo; cz <= zhi; cz++) {
            int adz = (cz > qz) ? (cz - qz) : (qz - cz);
            int ylo = max(qy - r, 0), yhi = min(qy + r, 31);
            for (int cy = ylo; cy <= yhi; cy++) {
                int ady = (cy > qy) ? (cy - qy) : (qy - cy);
                int xlo, xhi, xstep;
                if (adz == r || ady == r) {
                    xlo = max(qx - r, 0); xhi = min(qx + r, 31); xstep = 1;
                } else {
                    xlo = qx - r; xhi = qx + r; xstep = 2 * r;   // r >= 1 here
                }
                for (int cx = xlo; cx <= xhi; cx += xstep) {
                    if ((unsigned)cx > 31u) continue;
                    int cell = (cz * 32 + cy) * 32 + cx;
                    int s = st[cell], e = s + ct[cell];
                    for (int jj = s; jj < e; jj++) {
                        float4 k4 = kp[jj];
                        float dot = __fmul_rn(q.x, k4.x);
                        dot = fmaf(q.y, k4.y, dot);
                        dot = fmaf(q.z, k4.z, dot);
                        float d = __fadd_rn(fmaf(-2.0f, dot, q.w), k4.w);
                        int o = ko[jj];
                        if (d < bd) { bd = d; bi = o; }
                        else if (d == bd && o < bi) { bi = o; }
                    }
                }
            }
        }
    }
    g_idx[(size_t)b * N_ + oq] = bi;
}

// ---------------------------------------------------------------------------
// Tensor-core (tf32 mma.sync) fused GEMM body (unchanged from round 9).
// ---------------------------------------------------------------------------
template <int KDIM, bool GATHER, bool BN, bool STATS, bool TRANSOUT, int MTOT>
__device__ __forceinline__ void gemm_body(
    uint32_t* SH, int* idbuf,
    int b, int ob0, int ib0, int nbx, int bx,
    const float* __restrict__ W, int ldw, int woff,
    const float* __restrict__ X, int N,
    const float* __restrict__ P,
    const int*   __restrict__ idx,
    const float* __restrict__ bsc,
    const float* __restrict__ bbi,
    float* __restrict__ Y,
    float* __restrict__ part)
{
    const int t   = threadIdx.x;
    const int lane = t & 31, wid = t >> 5;
    const int wo = wid >> 1, wn = wid & 1;
    const int gid = lane >> 2, tig = lane & 3;

    const float* Wp = W + woff;
    const float* Xb = X + (size_t)b * KDIM * N;

    float acc[2][8][4];
#pragma unroll
    for (int m = 0; m < 2; m++)
#pragma unroll
        for (int n = 0; n < 8; n++)
#pragma unroll
            for (int e = 0; e < 4; e++) acc[m][n][e] = 0.f;

    const int w_o   = t >> 1;
    const int w_kq0 = (t & 1) * 16;
    const int w_mt  = w_o >> 4, w_gid = w_o & 7, w_hi = (w_o >> 3) & 1;

    const int x_k   = t >> 3;
    const int x_i0  = (t & 7) * 16;
    const int x_s   = x_k >> 3;
    const int x_tig = x_k & 3, x_hi = (x_k >> 2) & 1;

    constexpr int NKT = KDIM / 32;
    int buf = 0;
    for (int kt = 0; kt < NKT; ++kt) {
        const int k0 = kt * 32;
        uint32_t* Ab = SH + buf * 4096;
        uint32_t* Bb = SH + 8192 + buf * 4096;

        {
            const float* wr = Wp + (size_t)(ob0 + w_o) * ldw + k0 + w_kq0;
#pragma unroll
            for (int j = 0; j < 4; j++) {
                float4 v = *(const float4*)(wr + j * 4);
                uint32_t q[4] = {cvt_tf32(v.x), cvt_tf32(v.y), cvt_tf32(v.z), cvt_tf32(v.w)};
#pragma unroll
                for (int e = 0; e < 4; e++) {
                    int kk = w_kq0 + j * 4 + e;
                    int s = kk >> 3, c = kk & 7;
                    Ab[(((s * 8 + w_mt) * 32 + w_gid * 4 + (c & 3)) << 2)
                       + w_hi + ((c >> 2) << 1)] = q[e];
                }
            }
        }
        {
            const float* xr = Xb + (size_t)(k0 + x_k) * N + ib0 + x_i0;
            float bs = 0.f, bb = 0.f;
            if (BN) { bs = bsc[k0 + x_k]; bb = bbi[k0 + x_k]; }
#pragma unroll
            for (int j = 0; j < 4; j++) {
                float4 v = *(const float4*)(xr + j * 4);
                if (BN) {
                    v.x = fmaxf(fmaf(v.x, bs, bb), 0.f);
                    v.y = fmaxf(fmaf(v.y, bs, bb), 0.f);
                    v.z = fmaxf(fmaf(v.z, bs, bb), 0.f);
                    v.w = fmaxf(fmaf(v.w, bs, bb), 0.f);
                }
                uint32_t q[4] = {cvt_tf32(v.x), cvt_tf32(v.y), cvt_tf32(v.z), cvt_tf32(v.w)};
#pragma unroll
                for (int e = 0; e < 4; e++) {
                    int i = x_i0 + j * 4 + e;
                    int nt = i >> 3, gg = i & 7;
                    Bb[(((x_s * 8 + (nt >> 1)) * 32 + gg * 4 + x_tig) << 2)
                       + (nt & 1) * 2 + x_hi] = q[e];
                }
            }
        }
        __syncthreads();
#pragma unroll
        for (int s = 0; s < 4; s++) {
            uint4 af[2];
            af[0] = *(const uint4*)&Ab[((s * 8 + wo * 2 + 0) * 32 + lane) << 2];
            af[1] = *(const uint4*)&Ab[((s * 8 + wo * 2 + 1) * 32 + lane) << 2];
            uint4 bf[4];
#pragma unroll
            for (int p = 0; p < 4; p++)
                bf[p] = *(const uint4*)&Bb[((s * 8 + wn * 4 + p) * 32 + lane) << 2];
#pragma unroll
            for (int m = 0; m < 2; m++)
#pragma unroll
                for (int p = 0; p < 4; p++) {
                    mma_tf32(acc[m][2 * p],     (const uint32_t*)&af[m], bf[p].x, bf[p].y);
                    mma_tf32(acc[m][2 * p + 1], (const uint32_t*)&af[m], bf[p].z, bf[p].w);
                }
        }
        buf ^= 1;
    }

    const int o_base = ob0 + wo * 32;
    const int i_base = ib0 + wn * 64;

    if (GATHER) {
        __syncthreads();
        if (t < 128) idbuf[t] = idx[(size_t)b * N + ib0 + t];
        __syncthreads();
        float* G = (float*)SH;
#pragma unroll
        for (int j = 0; j < 16; j++) {
            int lin = t + j * 256;
            int r = lin >> 5, c4 = (lin & 31) << 2;
            const float* src = P + ((size_t)b * M_ + idbuf[r]) * MTOT + ob0 + c4;
            *(float4*)&G[r * 128 + c4] = *(const float4*)src;
        }
        __syncthreads();
        const int i0l = wn * 64 + tig * 2;
        const int o0l = wo * 32 + gid;
#pragma unroll
        for (int m = 0; m < 2; m++) {
            int oo = o0l + m * 16;
#pragma unroll
            for (int n = 0; n < 8; n++) {
                int ii = i0l + n * 8;
                acc[m][n][0] += G[ii * 128 + oo];
                acc[m][n][1] += G[(ii + 1) * 128 + oo];
                acc[m][n][2] += G[ii * 128 + oo + 8];
                acc[m][n][3] += G[(ii + 1) * 128 + oo + 8];
            }
        }
    }

    if (TRANSOUT) {
#pragma unroll
        for (int m = 0; m < 2; m++)
#pragma unroll
            for (int n = 0; n < 8; n++) {
                int i_ = i_base + n * 8 + tig * 2;
                int o_ = o_base + m * 16 + gid;
                float* Yr = Y + ((size_t)b * N + i_) * MTOT;
                Yr[o_]            = acc[m][n][0];
                Yr[MTOT + o_]     = acc[m][n][1];
                Yr[o_ + 8]        = acc[m][n][2];
                Yr[MTOT + o_ + 8] = acc[m][n][3];
            }
    } else {
#pragma unroll
        for (int m = 0; m < 2; m++) {
            float* Y0 = Y + ((size_t)b * MTOT + o_base + m * 16 + gid) * N + i_base + tig * 2;
            float* Y8 = Y0 + (size_t)8 * N;
#pragma unroll
            for (int n = 0; n < 8; n++) {
                *(float2*)(Y0 + n * 8) = make_float2(acc[m][n][0], acc[m][n][1]);
                *(float2*)(Y8 + n * 8) = make_float2(acc[m][n][2], acc[m][n][3]);
            }
        }
    }

    if (STATS) {
        float s1[2][2], s2[2][2];
#pragma unroll
        for (int m = 0; m < 2; m++) {
            float a0 = 0.f, q0 = 0.f, a1 = 0.f, q1 = 0.f;
#pragma unroll
            for (int n = 0; n < 8; n++) {
                a0 += acc[m][n][0]; q0 = fmaf(acc[m][n][0], acc[m][n][0], q0);
                a0 += acc[m][n][1]; q0 = fmaf(acc[m][n][1], acc[m][n][1], q0);
                a1 += acc[m][n][2]; q1 = fmaf(acc[m][n][2], acc[m][n][2], q1);
                a1 += acc[m][n][3]; q1 = fmaf(acc[m][n][3], acc[m][n][3], q1);
            }
            s1[m][0] = a0; s2[m][0] = q0; s1[m][1] = a1; s2[m][1] = q1;
        }
#pragma unroll
        for (int m = 0; m < 2; m++)
#pragma unroll
            for (int h = 0; h < 2; h++) {
#pragma unroll
                for (int off = 1; off <= 2; off <<= 1) {
                    s1[m][h] += __shfl_xor_sync(0xffffffffu, s1[m][h], off);
                    s2[m][h] += __shfl_xor_sync(0xffffffffu, s2[m][h], off);
                }
            }
        float* sb1 = (float*)SH;
        float* sb2 = sb1 + 256;
        __syncthreads();
        if (tig == 0) {
#pragma unroll
            for (int m = 0; m < 2; m++)
#pragma unroll
                for (int h = 0; h < 2; h++) {
                    int ol = wo * 32 + m * 16 + h * 8 + gid;
                    sb1[wn * 128 + ol] = s1[m][h];
                    sb2[wn * 128 + ol] = s2[m][h];
                }
        }
        __syncthreads();
        if (t < 128) {
            float tot = sb1[t] + sb1[128 + t];
            part[(((size_t)b * MTOT + ob0 + t) * nbx + bx) * 2 + 0] = tot;
        } else {
            int o = t - 128;
            float tot = sb2[o] + sb2[128 + o];
            part[(((size_t)b * MTOT + ob0 + o) * nbx + bx) * 2 + 1] = tot;
        }
    }
}

// ---------------------------------------------------------------------------
// Standalone GEMM kernel (K3, K5)
// ---------------------------------------------------------------------------
template <int KDIM, bool GATHER, bool BN, bool STATS, bool TRANSOUT, int MTOT>
__global__ void __launch_bounds__(256, 2) gemm_kernel(
    const float* __restrict__ W, int ldw, int woff,
    const float* __restrict__ X, int N,
    const float* __restrict__ P,
    const int*   __restrict__ idx,
    const float* __restrict__ bsc,
    const float* __restrict__ bbi,
    float* __restrict__ Y,
    float* __restrict__ part)
{
    __shared__ __align__(16) uint32_t SH[16384];
    __shared__ int idbuf[128];
    gemm_body<KDIM, GATHER, BN, STATS, TRANSOUT, MTOT>(
        SH, idbuf, blockIdx.z, blockIdx.y * 128, blockIdx.x * 128,
        gridDim.x, blockIdx.x,
        W, ldw, woff, X, N, P, idx, bsc, bbi, Y, part);
}

// ---------------------------------------------------------------------------
// FUSED kernel: bids [0,512) = grid-pruned 1-NN (256 queries/CTA);
//               bids [512,1024) = K2 (P_t = (w1a @ kf)^T).
// ---------------------------------------------------------------------------
__global__ void __launch_bounds__(256, 2) fused_nn_k2_kernel(
    const float* __restrict__ w1,
    const float* __restrict__ kf,
    float* __restrict__ P)
{
    __shared__ __align__(16) uint32_t SH[16384];
    __shared__ int idbuf[128];
    const int bid = blockIdx.x;
    if (bid < 512) {
        nn_search_body(bid * 256 + threadIdx.x);
    } else {
        const int g  = bid - 512;
        const int bx = g & 127;
        const int oy = (g >> 7) & 1;
        const int b  = g >> 8;
        gemm_body<C2_, false, false, false, true, H1_>(
            SH, idbuf, b, oy * 128, bx * 128, 128, bx,
            w1, 384, 0, kf, M_, nullptr, nullptr, nullptr, nullptr,
            P, nullptr);
    }
}

// ---------------------------------------------------------------------------
// Finalize BN stats: one block per channel
// ---------------------------------------------------------------------------
template <int MTOT>
__global__ void __launch_bounds__(128) fin_kernel(
    const float* __restrict__ part,
    const float* __restrict__ gamma, const float* __restrict__ beta,
    float* __restrict__ sc, float* __restrict__ bi, float invN)
{
    const int o = blockIdx.x;
    const int t = threadIdx.x;
    float s1 = 0.f, s2 = 0.f;
    for (int b = 0; b < B_; b++) {
        const float* p = part + ((size_t)b * MTOT + o) * NT_ * 2;
        for (int q = t; q < NT_; q += 128) {
            s1 += p[q * 2 + 0];
            s2 += p[q * 2 + 1];
        }
    }
#pragma unroll
    for (int off = 16; off; off >>= 1) {
        s1 += __shfl_down_sync(0xffffffffu, s1, off);
        s2 += __shfl_down_sync(0xffffffffu, s2, off);
    }
    __shared__ float r1[4], r2[4];
    if ((t & 31) == 0) { r1[t >> 5] = s1; r2[t >> 5] = s2; }
    __syncthreads();
    if (t == 0) {
        s1 = r1[0] + r1[1] + r1[2] + r1[3];
        s2 = r2[0] + r2[1] + r2[2] + r2[3];
        float mean = s1 * invN;
        float var  = s2 * invN - mean * mean;
        float rstd = rsqrtf(var + EPS_);
        float s    = gamma[o] * rstd;
        sc[o] = s;
        bi[o] = beta[o] - mean * s;
    }
}

// ---------------------------------------------------------------------------
// Final elementwise BN+ReLU in-place on d_out
// ---------------------------------------------------------------------------
__global__ void __launch_bounds__(256) bnfin_kernel(
    float* __restrict__ Y, const float* __restrict__ sc, const float* __restrict__ bi)
{
    int row = blockIdx.y;
    int ch  = row & (H2_ - 1);
    size_t base = (size_t)row * N_;
    int i = (blockIdx.x * 256 + threadIdx.x) * 4;
    float4 v = *(float4*)(Y + base + i);
    float s = sc[ch], b = bi[ch];
    v.x = fmaxf(fmaf(v.x, s, b), 0.f);
    v.y = fmaxf(fmaf(v.y, s, b), 0.f);
    v.z = fmaxf(fmaf(v.z, s, b), 0.f);
    v.w = fmaxf(fmaf(v.w, s, b), 0.f);
    *(float4*)(Y + base + i) = v;
}

// ---------------------------------------------------------------------------
// Launch
// ---------------------------------------------------------------------------
extern "C" void kernel_launch(void* const* d_in, const int* in_sizes, int n_in,
                              void* d_out, int out_size)
{
    const float* unknown = (const float*)d_in[0];
    const float* known   = (const float*)d_in[1];
    const float* uf      = (const float*)d_in[2];
    const float* kf      = (const float*)d_in[3];
    const float* w1      = (const float*)d_in[4];
    const float* gamma1  = (const float*)d_in[5];
    const float* beta1   = (const float*)d_in[6];
    const float* w2      = (const float*)d_in[7];
    const float* gamma2  = (const float*)d_in[8];
    const float* beta2   = (const float*)d_in[9];
    float* out = (float*)d_out;

    float *pP, *ph, *pp1, *pp2, *ps1, *pb1, *ps2, *pb2;
    int* pidx;
    cudaGetSymbolAddress((void**)&pP,   g_P);
    cudaGetSymbolAddress((void**)&ph,   g_h);
    cudaGetSymbolAddress((void**)&pp1,  g_part1);
    cudaGetSymbolAddress((void**)&pp2,  g_part2);
    cudaGetSymbolAddress((void**)&ps1,  g_scale1);
    cudaGetSymbolAddress((void**)&pb1,  g_bias1);
    cudaGetSymbolAddress((void**)&ps2,  g_scale2);
    cudaGetSymbolAddress((void**)&pb2,  g_bias2);
    cudaGetSymbolAddress((void**)&pidx, g_idx);

    const float invN = 1.0f / (float)(B_ * N_);

    // grid binning for pruned 1-NN
    zero_kernel<<<256, 256>>>();
    hist_kernel<<<(B_ * (M_ + N_)) / 256, 256>>>(unknown, known);
    scan_kernel<<<4, 1024>>>();
    scatter_kernel<<<(B_ * (M_ + N_)) / 256, 256>>>(unknown, known);

    // 1-NN (bids 0..511) + K2 P_t-GEMM (bids 512..1023) in one launch
    fused_nn_k2_kernel<<<1024, 256>>>(w1, kf, pP);

    // h = w1[:, 256:] @ unknow_feats + gather(P_t, idx); stats1
    gemm_kernel<C1_, true, false, true, false, H1_>
        <<<dim3(N_ / 128, H1_ / 128, B_), 256>>>(
            w1, 384, C2_, uf, N_, pP, pidx, nullptr, nullptr, ph, pp1);

    fin_kernel<H1_><<<H1_, 128>>>(pp1, gamma1, beta1, ps1, pb1, invN);

    // out_pre = w2 @ relu(bn1(h)); stats2
    gemm_kernel<H1_, false, true, true, false, H2_>
        <<<dim3(N_ / 128, H2_ / 128, B_), 256>>>(
            w2, 256, 0, ph, N_, nullptr, nullptr, ps1, pb1, out, pp2);

    fin_kernel<H2_><<<H2_, 128>>>(pp2, gamma2, beta2, ps2, pb2, invN);

    bnfin_kernel<<<dim3(N_ / 1024, B_ * H2_), 256>>>(out, ps2, pb2);
}